// round 1
// baseline (speedup 1.0000x reference)
#include <cuda_runtime.h>
#include <math.h>

constexpr int B = 8, N1 = 64, N2 = 512, D = 128, NL = 3, H = 128, NT = 7;

// ---------------- scratch (static device memory; no runtime allocation) ----
constexpr size_t SZ_H1   = (size_t)B * N1 * D;      // 65536
constexpr size_t SZ_H2   = (size_t)B * N2 * D;      // 524288
constexpr size_t SZ_ATT1 = (size_t)B * N1 * N1;     // 32768
constexpr size_t SZ_ATT2 = (size_t)B * N2 * N2;     // 2097152
constexpr size_t SZ_U1   = (size_t)B * N1 * NT * H; // 458752
constexpr size_t SZ_U2   = (size_t)B * N2 * NT * H; // 3670016
constexpr size_t SZ_DM   = (size_t)B * N1 * N2;     // 262144
constexpr size_t SZ_EP   = (size_t)B * NT * N1;     // 3584

constexpr size_t OFF_H1A  = 0;
constexpr size_t OFF_H1B  = OFF_H1A  + SZ_H1;
constexpr size_t OFF_H2A  = OFF_H1B  + SZ_H1;
constexpr size_t OFF_H2B  = OFF_H2A  + SZ_H2;
constexpr size_t OFF_T1   = OFF_H2B  + SZ_H2;   // h   (graph1)
constexpr size_t OFF_TA1  = OFF_T1   + SZ_H1;   // hA  (graph1)
constexpr size_t OFF_T2   = OFF_TA1  + SZ_H1;   // h   (graph2)
constexpr size_t OFF_TA2  = OFF_T2   + SZ_H2;   // hA  (graph2)
constexpr size_t OFF_ATT1 = OFF_TA2  + SZ_H2;
constexpr size_t OFF_ATT2 = OFF_ATT1 + SZ_ATT1;
constexpr size_t OFF_U1A  = OFF_ATT2 + SZ_ATT2;
constexpr size_t OFF_U1B  = OFF_U1A  + SZ_U1;
constexpr size_t OFF_U2A  = OFF_U1B  + SZ_U1;
constexpr size_t OFF_U2B  = OFF_U2A  + SZ_U2;
constexpr size_t OFF_DM   = OFF_U2B  + SZ_U2;
constexpr size_t OFF_EP   = OFF_DM   + SZ_DM;
constexpr size_t SCRATCH_TOTAL = OFF_EP + SZ_EP;

__device__ float g_scratch[SCRATCH_TOTAL];

__constant__ float c_bconstraint[NT] = {1.159f, 0.448f, 0.927f, 0.902f, 0.349f, 0.789f, 0.198f};

__device__ __forceinline__ float sigmoidf(float x) { return 1.f / (1.f + expf(-x)); }

// ---------------- embedding: out[r,:] = x[r,:56] @ W[56,128] ---------------
template <int TM>
__global__ void k_embed(const float* __restrict__ x, const float* __restrict__ W,
                        float* __restrict__ out) {
    int r0 = blockIdx.x * TM;
    int t  = threadIdx.x;                // 128 threads = output col
    __shared__ float xs[TM][56];
    for (int idx = t; idx < TM * 56; idx += 128) {
        int m = idx / 56, d = idx % 56;
        xs[m][d] = x[(size_t)(r0 + m) * 56 + d];
    }
    __syncthreads();
    float acc[TM];
#pragma unroll
    for (int m = 0; m < TM; m++) acc[m] = 0.f;
    for (int k = 0; k < 56; k++) {
        float wv = W[k * 128 + t];
#pragma unroll
        for (int m = 0; m < TM; m++) acc[m] = fmaf(xs[m][k], wv, acc[m]);
    }
#pragma unroll
    for (int m = 0; m < TM; m++) out[(size_t)(r0 + m) * 128 + t] = acc[m];
}

// ---------------- h = x@W + Wb ; hA = h@A  (row-tiled) ----------------------
template <int TM>
__global__ void k_h_hA(const float* __restrict__ x, const float* __restrict__ W,
                       const float* __restrict__ Wb, const float* __restrict__ A,
                       float* __restrict__ h, float* __restrict__ hA) {
    int r0 = blockIdx.x * TM;
    int t  = threadIdx.x;                // 128
    __shared__ float xs[TM][128];
    __shared__ float hs[TM][128];
#pragma unroll
    for (int m = 0; m < TM; m++) xs[m][t] = x[(size_t)(r0 + m) * 128 + t];
    __syncthreads();
    float acc[TM];
    float wb = Wb[t];
#pragma unroll
    for (int m = 0; m < TM; m++) acc[m] = wb;
    for (int k = 0; k < 128; k++) {
        float wv = W[k * 128 + t];
#pragma unroll
        for (int m = 0; m < TM; m++) acc[m] = fmaf(xs[m][k], wv, acc[m]);
    }
#pragma unroll
    for (int m = 0; m < TM; m++) {
        h[(size_t)(r0 + m) * 128 + t] = acc[m];
        hs[m][t] = acc[m];
    }
    __syncthreads();
    float acc2[TM];
#pragma unroll
    for (int m = 0; m < TM; m++) acc2[m] = 0.f;
    for (int k = 0; k < 128; k++) {
        float av = A[k * 128 + t];
#pragma unroll
        for (int m = 0; m < TM; m++) acc2[m] = fmaf(hs[m][k], av, acc2[m]);
    }
#pragma unroll
    for (int m = 0; m < TM; m++) hA[(size_t)(r0 + m) * 128 + t] = acc2[m];
}

// ---- att kernel: e'[j,k] = hA_j·h_k + hA_k·h_j ; mask ; softmax over j ; *adj
// one block per (b, 16-column tile); 256 threads = 8 warps
template <int N, int TK>
__global__ void k_att(const float* __restrict__ h, const float* __restrict__ hA,
                      const float* __restrict__ adj, float* __restrict__ att) {
    constexpr int TILES = N / TK;
    int b  = blockIdx.x / TILES;
    int k0 = (blockIdx.x % TILES) * TK;
    int t = threadIdx.x, lane = t & 31, w = t >> 5;
    __shared__ float hk[TK][128];
    __shared__ float hAk[TK][128];
    __shared__ float ecol[TK][N];
    for (int idx = t; idx < TK * 128; idx += 256) {
        int kk = idx >> 7, d = idx & 127;
        hk[kk][d]  = h [((size_t)b * N + k0 + kk) * 128 + d];
        hAk[kk][d] = hA[((size_t)b * N + k0 + kk) * 128 + d];
    }
    __syncthreads();
    for (int j = w; j < N; j += 8) {
        const float* hj  = h  + ((size_t)b * N + j) * 128;
        const float* hAj = hA + ((size_t)b * N + j) * 128;
        float hjv[4], hAjv[4];
#pragma unroll
        for (int q = 0; q < 4; q++) { hjv[q] = hj[lane + 32 * q]; hAjv[q] = hAj[lane + 32 * q]; }
#pragma unroll
        for (int kk = 0; kk < TK; kk++) {
            float v = 0.f;
#pragma unroll
            for (int q = 0; q < 4; q++) {
                int d = lane + 32 * q;
                v = fmaf(hAjv[q], hk[kk][d], v);
                v = fmaf(hjv[q], hAk[kk][d], v);
            }
#pragma unroll
            for (int o = 16; o; o >>= 1) v += __shfl_down_sync(0xffffffffu, v, o);
            if (lane == 0) {
                float a = adj[((size_t)b * N + j) * N + (k0 + kk)];
                ecol[kk][j] = (a > 0.f) ? v : -9e15f;
            }
        }
    }
    __syncthreads();
    // softmax over j for each column; one warp per column (kk = w, w+8)
    for (int kk = w; kk < TK; kk += 8) {
        float m = -INFINITY;
        for (int j = lane; j < N; j += 32) m = fmaxf(m, ecol[kk][j]);
#pragma unroll
        for (int o = 16; o; o >>= 1) m = fmaxf(m, __shfl_xor_sync(0xffffffffu, m, o));
        float s = 0.f;
        for (int j = lane; j < N; j += 32) {
            float e = expf(ecol[kk][j] - m);
            ecol[kk][j] = e;
            s += e;
        }
#pragma unroll
        for (int o = 16; o; o >>= 1) s += __shfl_xor_sync(0xffffffffu, s, o);
        float inv = 1.f / s;
        for (int j = lane; j < N; j += 32) {
            float a = adj[((size_t)b * N + j) * N + (k0 + kk)];
            att[((size_t)b * N + j) * N + (k0 + kk)] = ecol[kk][j] * inv * a;
        }
    }
}

// ---- hp = relu(att@h) ; coeff = sigmoid([x,hp]@Wg+bg) ; out = c*x+(1-c)*hp -
template <int N, int TM>
__global__ void k_hp_gate(const float* __restrict__ x, const float* __restrict__ h,
                          const float* __restrict__ att, const float* __restrict__ Wg,
                          const float* __restrict__ bg, float* __restrict__ out) {
    constexpr int TILES = N / TM;
    int b  = blockIdx.x / TILES;
    int n0 = (blockIdx.x % TILES) * TM;
    int t = threadIdx.x, lane = t & 31, w = t >> 5;  // 128 threads
    __shared__ float atts[TM][N];
    __shared__ float partial[TM][4];
    __shared__ float coeff[TM];
#pragma unroll
    for (int m = 0; m < TM; m++)
        for (int j = t; j < N; j += 128)
            atts[m][j] = att[((size_t)b * N + n0 + m) * N + j];
    __syncthreads();
    float acc[TM];
#pragma unroll
    for (int m = 0; m < TM; m++) acc[m] = 0.f;
    const float* hb = h + (size_t)b * N * 128;
    for (int j = 0; j < N; j++) {
        float hv = hb[(size_t)j * 128 + t];
#pragma unroll
        for (int m = 0; m < TM; m++) acc[m] = fmaf(atts[m][j], hv, acc[m]);
    }
    float xr[TM];
    float wg0 = Wg[t], wg1 = Wg[128 + t];
#pragma unroll
    for (int m = 0; m < TM; m++) {
        acc[m] = fmaxf(acc[m], 0.f);                       // relu(hp)
        xr[m]  = x[((size_t)b * N + n0 + m) * 128 + t];
        float v = xr[m] * wg0 + acc[m] * wg1;
#pragma unroll
        for (int o = 16; o; o >>= 1) v += __shfl_down_sync(0xffffffffu, v, o);
        if (lane == 0) partial[m][w] = v;
    }
    __syncthreads();
    if (t < TM) {
        float s = partial[t][0] + partial[t][1] + partial[t][2] + partial[t][3] + bg[0];
        coeff[t] = sigmoidf(s);
    }
    __syncthreads();
#pragma unroll
    for (int m = 0; m < TM; m++) {
        float c = coeff[m];
        out[((size_t)b * N + n0 + m) * 128 + t] = c * xr[m] + (1.f - c) * acc[m];
    }
}

// ---------------- pairwise-distance matrix ---------------------------------
__global__ void k_dm(const float* __restrict__ dmv, float* __restrict__ dm, int n) {
    int i = blockIdx.x * blockDim.x + threadIdx.x;
    if (i < n) {
        float xx = dmv[3 * (size_t)i + 0];
        float yy = dmv[3 * (size_t)i + 1];
        float zz = dmv[3 * (size_t)i + 2];
        float d = sqrtf(xx * xx + yy * yy + zz * zz + 1e-10f);
        dm[i] = (d < 0.5f) ? 1e10f : d;
    }
}

// ---- U precompute: U{A,B}[row,i,:] = x[row,:]@W{A,B}1[i, dOff:dOff+128, :] (+bias)
template <int TM>
__global__ void k_precU(const float* __restrict__ x,
                        const float* __restrict__ WA1, const float* __restrict__ bA1,
                        const float* __restrict__ WB1, const float* __restrict__ bB1,
                        int tilesPerI, int dOff, int addBias,
                        float* __restrict__ UA, float* __restrict__ UB) {
    int i  = blockIdx.x / tilesPerI;
    int r0 = (blockIdx.x % tilesPerI) * TM;
    int hh = threadIdx.x;                   // 128
    __shared__ float xs[TM][128];
#pragma unroll
    for (int m = 0; m < TM; m++) xs[m][hh] = x[(size_t)(r0 + m) * 128 + hh];
    __syncthreads();
    float ba = addBias ? bA1[i * 128 + hh] : 0.f;
    float bb = addBias ? bB1[i * 128 + hh] : 0.f;
    float accA[TM], accB[TM];
#pragma unroll
    for (int m = 0; m < TM; m++) { accA[m] = ba; accB[m] = bb; }
    const float* wa = WA1 + ((size_t)i * 256 + dOff) * 128;
    const float* wb = WB1 + ((size_t)i * 256 + dOff) * 128;
    for (int d = 0; d < 128; d++) {
        float wav = wa[(size_t)d * 128 + hh];
        float wbv = wb[(size_t)d * 128 + hh];
#pragma unroll
        for (int m = 0; m < TM; m++) {
            accA[m] = fmaf(xs[m][d], wav, accA[m]);
            accB[m] = fmaf(xs[m][d], wbv, accB[m]);
        }
    }
#pragma unroll
    for (int m = 0; m < TM; m++) {
        UA[((size_t)(r0 + m) * NT + i) * 128 + hh] = accA[m];
        UB[((size_t)(r0 + m) * NT + i) * 128 + hh] = accB[m];
    }
}

// ---------------- intercept: writes out[b,0..6] = sig(..)*4/7 ---------------
__global__ void k_intercept(const float* __restrict__ h1e, const float* __restrict__ valid,
                            const float* __restrict__ Wi1, const float* __restrict__ bi1,
                            const float* __restrict__ Wi2, const float* __restrict__ bi2,
                            float* __restrict__ out) {
    int b = blockIdx.x, t = threadIdx.x;   // 128 threads
    int lane = t & 31, w = t >> 5;
    __shared__ float pooled[128];
    __shared__ float red[4];
    float p = 0.f;
    for (int j = 0; j < N1; j++)
        p = fmaf(h1e[((size_t)b * N1 + j) * 128 + t], valid[b * N1 + j], p);
    pooled[t] = p;
    __syncthreads();
    float acc = bi1[t];
    for (int d = 0; d < 128; d++) acc = fmaf(pooled[d], Wi1[d * 128 + t], acc);
    float v = fmaxf(acc, 0.f) * Wi2[t];
#pragma unroll
    for (int o = 16; o; o >>= 1) v += __shfl_down_sync(0xffffffffu, v, o);
    if (lane == 0) red[w] = v;
    __syncthreads();
    if (t == 0) {
        float s = red[0] + red[1] + red[2] + red[3] + bi2[0];
        s = 4.f * sigmoidf(s);
        float val = s / 7.f;
        for (int i = 0; i < NT; i++) out[b * NT + i] = val;
    }
}

// ---- sparse energy: block per (b,i,j); warps iterate k, skip A_int==0 ------
__global__ void k_energy(const float* __restrict__ U1A, const float* __restrict__ U1B,
                         const float* __restrict__ U2A, const float* __restrict__ U2B,
                         const float* __restrict__ WA2, const float* __restrict__ bA2,
                         const float* __restrict__ WB2, const float* __restrict__ bB2,
                         const float* __restrict__ Cc, const float* __restrict__ A_int,
                         const float* __restrict__ dm, float* __restrict__ epart) {
    int j  = blockIdx.x % N1;
    int bi = blockIdx.x / N1;
    int i  = bi % NT;
    int b  = bi / NT;
    int t = threadIdx.x, lane = t & 31, w = t >> 5;  // 128 threads / 4 warps
    __shared__ float u1a[128], u1b[128], wa2[128], wb2[128];
    __shared__ float part[4];
    u1a[t] = U1A[(((size_t)b * N1 + j) * NT + i) * 128 + t];
    u1b[t] = U1B[(((size_t)b * N1 + j) * NT + i) * 128 + t];
    wa2[t] = WA2[i * 128 + t];
    wb2[t] = WB2[i * 128 + t];
    __syncthreads();
    float bc = c_bconstraint[i];
    float bcinv = 1.f / (3.f * bc * bc);
    float Ci = Cc[i], ba2 = bA2[i], bb2 = bB2[i];
    const float* aint_row = A_int + (((size_t)b * NT + i) * N1 + j) * N2;
    const float* dm_row   = dm + ((size_t)b * N1 + j) * N2;
    float esum = 0.f;
    for (int k = w; k < N2; k += 4) {
        float av = aint_row[k];
        if (av != 0.f) {
            const float* u2a = U2A + (((size_t)b * N2 + k) * NT + i) * 128;
            const float* u2b = U2B + (((size_t)b * N2 + k) * NT + i) * 128;
            float sA = 0.f, sB = 0.f;
#pragma unroll
            for (int q = 0; q < 4; q++) {
                int hh = lane + 32 * q;
                sA = fmaf(fmaxf(u1a[hh] + u2a[hh], 0.f), wa2[hh], sA);
                sB = fmaf(fmaxf(u1b[hh] + u2b[hh], 0.f), wb2[hh], sB);
            }
#pragma unroll
            for (int o = 16; o; o >>= 1) {
                sA += __shfl_xor_sync(0xffffffffu, sA, o);
                sB += __shfl_xor_sync(0xffffffffu, sB, o);
            }
            if (lane == 0) {
                float Aa = 4.f * sigmoidf(sA + ba2);
                float Bp = sigmoidf(sB + bb2) * (2.f * bcinv) + bcinv;
                float dd = dm_row[k] - Ci;
                esum += Aa * (Bp * dd * dd - 1.f) * av;
            }
        }
    }
    if (lane == 0) part[w] = esum;
    __syncthreads();
    if (t == 0) epart[blockIdx.x] = part[0] + part[1] + part[2] + part[3];
}

// ---------------- final deterministic reduction -----------------------------
__global__ void k_reduce(const float* __restrict__ epart, float* __restrict__ out) {
    int t = threadIdx.x;
    if (t < B * NT) {
        float s = 0.f;
        for (int j = 0; j < N1; j++) s += epart[(size_t)t * N1 + j];
        out[t] += s;
    }
}

// ---------------- launch orchestration --------------------------------------
extern "C" void kernel_launch(void* const* d_in, const int* in_sizes, int n_in,
                              void* d_out, int out_size) {
    const float* h1     = (const float*)d_in[0];
    const float* adj1   = (const float*)d_in[1];
    const float* h2     = (const float*)d_in[2];
    const float* adj2   = (const float*)d_in[3];
    const float* A_int  = (const float*)d_in[4];
    const float* dmv    = (const float*)d_in[5];
    const float* valid  = (const float*)d_in[6];
    const float* W_embed= (const float*)d_in[7];
    const float* gW     = (const float*)d_in[8];
    const float* gWb    = (const float*)d_in[9];
    const float* gA     = (const float*)d_in[10];
    const float* gGateW = (const float*)d_in[11];
    const float* gGateb = (const float*)d_in[12];
    const float* WA1    = (const float*)d_in[13];
    const float* bA1    = (const float*)d_in[14];
    const float* WA2    = (const float*)d_in[15];
    const float* bA2    = (const float*)d_in[16];
    const float* WB1    = (const float*)d_in[17];
    const float* bB1    = (const float*)d_in[18];
    const float* WB2    = (const float*)d_in[19];
    const float* bB2    = (const float*)d_in[20];
    const float* Cc     = (const float*)d_in[21];
    const float* Wi1    = (const float*)d_in[22];
    const float* bi1    = (const float*)d_in[23];
    const float* Wi2    = (const float*)d_in[24];
    const float* bi2    = (const float*)d_in[25];
    float* out = (float*)d_out;

    float* S = nullptr;
    cudaGetSymbolAddress((void**)&S, g_scratch);

    float* h1buf[2] = {S + OFF_H1A, S + OFF_H1B};
    float* h2buf[2] = {S + OFF_H2A, S + OFF_H2B};
    float* t1  = S + OFF_T1;
    float* ta1 = S + OFF_TA1;
    float* t2  = S + OFF_T2;
    float* ta2 = S + OFF_TA2;
    float* att1 = S + OFF_ATT1;
    float* att2 = S + OFF_ATT2;
    float* U1A = S + OFF_U1A;
    float* U1B = S + OFF_U1B;
    float* U2A = S + OFF_U2A;
    float* U2B = S + OFF_U2B;
    float* dmS = S + OFF_DM;
    float* ep  = S + OFF_EP;

    // 1. embed
    k_embed<8><<<B * N1 / 8, 128>>>(h1, W_embed, h1buf[0]);
    k_embed<8><<<B * N2 / 8, 128>>>(h2, W_embed, h2buf[0]);

    // 2. GAT layers
    int cur = 0;
    for (int l = 0; l < NL; l++) {
        const float* W  = gW + (size_t)l * D * D;
        const float* Wb = gWb + (size_t)l * D;
        const float* A  = gA + (size_t)l * D * D;
        const float* Gw = gGateW + (size_t)l * 2 * D;
        const float* Gb = gGateb + l;
        int nxt = cur ^ 1;
        // graph 1 (N1=64)
        k_h_hA<8><<<B * N1 / 8, 128>>>(h1buf[cur], W, Wb, A, t1, ta1);
        k_att<N1, 16><<<B * (N1 / 16), 256>>>(t1, ta1, adj1, att1);
        k_hp_gate<N1, 8><<<B * N1 / 8, 128>>>(h1buf[cur], t1, att1, Gw, Gb, h1buf[nxt]);
        // graph 2 (N2=512)
        k_h_hA<8><<<B * N2 / 8, 128>>>(h2buf[cur], W, Wb, A, t2, ta2);
        k_att<N2, 16><<<B * (N2 / 16), 256>>>(t2, ta2, adj2, att2);
        k_hp_gate<N2, 8><<<B * N2 / 8, 128>>>(h2buf[cur], t2, att2, Gw, Gb, h2buf[nxt]);
        cur = nxt;
    }
    const float* h1e = h1buf[cur];
    const float* h2e = h2buf[cur];

    // 3. precompute factored MLP-first-layer terms
    k_precU<16><<<NT * (B * N1 / 16), 128>>>(h1e, WA1, bA1, WB1, bB1,
                                             B * N1 / 16, 0, 1, U1A, U1B);
    k_precU<16><<<NT * (B * N2 / 16), 128>>>(h2e, WA1, bA1, WB1, bB1,
                                             B * N2 / 16, 128, 0, U2A, U2B);

    // 4. distances
    k_dm<<<(B * N1 * N2 + 255) / 256, 256>>>(dmv, dmS, B * N1 * N2);

    // 5. intercept (initializes out), sparse energies, deterministic reduce
    k_intercept<<<B, 128>>>(h1e, valid, Wi1, bi1, Wi2, bi2, out);
    k_energy<<<B * NT * N1, 128>>>(U1A, U1B, U2A, U2B, WA2, bA2, WB2, bB2,
                                   Cc, A_int, dmS, ep);
    k_reduce<<<1, 64>>>(ep, out);
}

// round 4
// speedup vs baseline: 2.1795x; 2.1795x over previous
#include <cuda_runtime.h>
#include <math.h>

constexpr int B = 8, N1 = 64, N2 = 512, D = 128, NL = 3, H = 128, NT = 7;

// ---------------- scratch (static device memory) ----------------------------
constexpr size_t SZ_H1   = (size_t)B * N1 * D;
constexpr size_t SZ_H2   = (size_t)B * N2 * D;
constexpr size_t SZ_ATT1 = (size_t)B * N1 * N1;
constexpr size_t SZ_ATT2 = (size_t)B * N2 * N2;
constexpr size_t SZ_G1   = SZ_ATT1;
constexpr size_t SZ_G2   = SZ_ATT2;
constexpr size_t SZ_U1   = (size_t)B * N1 * NT * H;
constexpr size_t SZ_U2   = (size_t)B * N2 * NT * H;
constexpr size_t SZ_DM   = (size_t)B * N1 * N2;
constexpr size_t SZ_EP   = (size_t)B * NT * N1;

constexpr size_t OFF_H1A  = 0;
constexpr size_t OFF_H1B  = OFF_H1A  + SZ_H1;
constexpr size_t OFF_H2A  = OFF_H1B  + SZ_H1;
constexpr size_t OFF_H2B  = OFF_H2A  + SZ_H2;
constexpr size_t OFF_T1   = OFF_H2B  + SZ_H2;
constexpr size_t OFF_TA1  = OFF_T1   + SZ_H1;
constexpr size_t OFF_T2   = OFF_TA1  + SZ_H1;
constexpr size_t OFF_TA2  = OFF_T2   + SZ_H2;
constexpr size_t OFF_ATT1 = OFF_TA2  + SZ_H2;
constexpr size_t OFF_ATT2 = OFF_ATT1 + SZ_ATT1;
constexpr size_t OFF_G1   = OFF_ATT2 + SZ_ATT2;
constexpr size_t OFF_G2   = OFF_G1   + SZ_G1;
constexpr size_t OFF_U1A  = OFF_G2   + SZ_G2;
constexpr size_t OFF_U1B  = OFF_U1A  + SZ_U1;
constexpr size_t OFF_U2A  = OFF_U1B  + SZ_U1;
constexpr size_t OFF_U2B  = OFF_U2A  + SZ_U2;
constexpr size_t OFF_DM   = OFF_U2B  + SZ_U2;
constexpr size_t OFF_EP   = OFF_DM   + SZ_DM;
constexpr size_t SCRATCH_TOTAL = OFF_EP + SZ_EP;

__device__ float g_scratch[SCRATCH_TOTAL];

__constant__ float c_bconstraint[NT] = {1.159f, 0.448f, 0.927f, 0.902f, 0.349f, 0.789f, 0.198f};

__device__ __forceinline__ float sigmoidf(float x) { return 1.f / (1.f + expf(-x)); }

// ---------------- packed fp32x2 helpers (sm_103a dual-fp32 pipe) ------------
__device__ __forceinline__ unsigned long long pack2(float lo, float hi) {
    unsigned long long r;
    asm("mov.b64 %0, {%1,%2};" : "=l"(r) : "f"(lo), "f"(hi));
    return r;
}
__device__ __forceinline__ void unpack2(unsigned long long v, float& lo, float& hi) {
    asm("mov.b64 {%0,%1}, %2;" : "=f"(lo), "=f"(hi) : "l"(v));
}
__device__ __forceinline__ void fma2(unsigned long long& d, unsigned long long a,
                                     unsigned long long b) {
    asm("fma.rn.f32x2 %0, %1, %2, %0;" : "+l"(d) : "l"(a), "l"(b));
}
__device__ __forceinline__ unsigned long long lds2(const float* p) {
    return *reinterpret_cast<const unsigned long long*>(p);
}

// ---------------- embedding (both graphs, one launch) ------------------------
template <int TM>
__global__ void k_embed(const float* __restrict__ x1, const float* __restrict__ x2,
                        const float* __restrict__ W,
                        float* __restrict__ o1, float* __restrict__ o2) {
    constexpr int T1 = (B * N1) / TM;
    int blk = blockIdx.x;
    const float* x; float* out; int r0;
    if (blk < T1) { x = x1; out = o1; r0 = blk * TM; }
    else          { x = x2; out = o2; r0 = (blk - T1) * TM; }
    int t = threadIdx.x;
    __shared__ float xs[TM][56];
    for (int idx = t; idx < TM * 56; idx += 128) {
        int m = idx / 56, d = idx % 56;
        xs[m][d] = x[(size_t)(r0 + m) * 56 + d];
    }
    __syncthreads();
    float acc[TM];
#pragma unroll
    for (int m = 0; m < TM; m++) acc[m] = 0.f;
    for (int k = 0; k < 56; k++) {
        float wv = W[k * 128 + t];
#pragma unroll
        for (int m = 0; m < TM; m++) acc[m] = fmaf(xs[m][k], wv, acc[m]);
    }
#pragma unroll
    for (int m = 0; m < TM; m++) out[(size_t)(r0 + m) * 128 + t] = acc[m];
}

// ---------------- h = x@W + Wb ; hA = h@A  (merged, packed f32x2) ------------
template <int TM>   // TM must be even
__global__ void __launch_bounds__(128)
k_h_hA(const float* __restrict__ x1, const float* __restrict__ x2,
       const float* __restrict__ W, const float* __restrict__ Wb,
       const float* __restrict__ A,
       float* __restrict__ h1o, float* __restrict__ hA1o,
       float* __restrict__ h2o, float* __restrict__ hA2o) {
    constexpr int T1 = (B * N1) / TM;
    int blk = blockIdx.x;
    const float* x; float *ho, *hAo; int r0;
    if (blk < T1) { x = x1; ho = h1o; hAo = hA1o; r0 = blk * TM; }
    else          { x = x2; ho = h2o; hAo = hA2o; r0 = (blk - T1) * TM; }
    int t = threadIdx.x;
    __shared__ float xsT[128][TM + 2];
    __shared__ float hsT[128][TM + 2];
#pragma unroll
    for (int m = 0; m < TM; m++) xsT[t][m] = x[(size_t)(r0 + m) * 128 + t];
    __syncthreads();
    unsigned long long acc[TM / 2];
    float wb = Wb[t];
#pragma unroll
    for (int p = 0; p < TM / 2; p++) acc[p] = pack2(wb, wb);
    for (int k = 0; k < 128; k++) {
        float wv = W[k * 128 + t];
        unsigned long long w2 = pack2(wv, wv);
#pragma unroll
        for (int p = 0; p < TM / 2; p++) fma2(acc[p], lds2(&xsT[k][2 * p]), w2);
    }
#pragma unroll
    for (int p = 0; p < TM / 2; p++) {
        float lo, hi; unpack2(acc[p], lo, hi);
        ho[(size_t)(r0 + 2 * p) * 128 + t] = lo;
        ho[(size_t)(r0 + 2 * p + 1) * 128 + t] = hi;
        hsT[t][2 * p] = lo; hsT[t][2 * p + 1] = hi;
    }
    __syncthreads();
#pragma unroll
    for (int p = 0; p < TM / 2; p++) acc[p] = 0ull;
    for (int k = 0; k < 128; k++) {
        float av = A[k * 128 + t];
        unsigned long long a2 = pack2(av, av);
#pragma unroll
        for (int p = 0; p < TM / 2; p++) fma2(acc[p], lds2(&hsT[k][2 * p]), a2);
    }
#pragma unroll
    for (int p = 0; p < TM / 2; p++) {
        float lo, hi; unpack2(acc[p], lo, hi);
        hAo[(size_t)(r0 + 2 * p) * 128 + t] = lo;
        hAo[(size_t)(r0 + 2 * p + 1) * 128 + t] = hi;
    }
}

// ---------------- G = hA @ h^T  (register-tiled GEMM, both graphs) -----------
constexpr int BJ = 128, BK = 64, DKK = 16;
__global__ void __launch_bounds__(256)
k_gemmG(const float* __restrict__ hA2, const float* __restrict__ h2, float* __restrict__ G2,
        const float* __restrict__ hA1, const float* __restrict__ h1, float* __restrict__ G1) {
    int blk = blockIdx.x;
    const float *hA, *hh; float* G; int N, b, j0, k0;
    if (blk < 256) { N = 512; b = blk >> 5; j0 = ((blk >> 3) & 3) * BJ; k0 = (blk & 7) * BK;
                     hA = hA2; hh = h2; G = G2; }
    else           { N = 64; b = blk - 256; j0 = 0; k0 = 0; hA = hA1; hh = h1; G = G1; }
    int t = threadIdx.x;
    int tx = t & 15, ty = t >> 4;
    __shared__ float As[DKK][BJ + 4];
    __shared__ float Bs[DKK][BK + 4];
    unsigned long long acc[4][4];
#pragma unroll
    for (int p = 0; p < 4; p++)
#pragma unroll
        for (int q = 0; q < 4; q++) acc[p][q] = 0ull;

    for (int dc = 0; dc < 128; dc += DKK) {
#pragma unroll
        for (int i = 0; i < 2; i++) {
            int idx = t + i * 256;
            int jrow = idx >> 2, dq = idx & 3;
            float4 v;
            if (j0 + jrow < N)
                v = *reinterpret_cast<const float4*>(&hA[((size_t)b * N + j0 + jrow) * 128 + dc + dq * 4]);
            else v = make_float4(0.f, 0.f, 0.f, 0.f);
            As[dq * 4 + 0][jrow] = v.x; As[dq * 4 + 1][jrow] = v.y;
            As[dq * 4 + 2][jrow] = v.z; As[dq * 4 + 3][jrow] = v.w;
        }
        {
            int krow = t >> 2, dq = t & 3;
            float4 v = *reinterpret_cast<const float4*>(&hh[((size_t)b * N + k0 + krow) * 128 + dc + dq * 4]);
            Bs[dq * 4 + 0][krow] = v.x; Bs[dq * 4 + 1][krow] = v.y;
            Bs[dq * 4 + 2][krow] = v.z; Bs[dq * 4 + 3][krow] = v.w;
        }
        __syncthreads();
#pragma unroll
        for (int d = 0; d < DKK; d++) {
            unsigned long long a2[4];
#pragma unroll
            for (int p = 0; p < 4; p++) a2[p] = lds2(&As[d][ty * 8 + 2 * p]);
            float4 bv = *reinterpret_cast<const float4*>(&Bs[d][tx * 4]);
            unsigned long long b2[4] = {pack2(bv.x, bv.x), pack2(bv.y, bv.y),
                                        pack2(bv.z, bv.z), pack2(bv.w, bv.w)};
#pragma unroll
            for (int p = 0; p < 4; p++)
#pragma unroll
                for (int q = 0; q < 4; q++) fma2(acc[p][q], a2[p], b2[q]);
        }
        __syncthreads();
    }
#pragma unroll
    for (int p = 0; p < 4; p++) {
        int j = j0 + ty * 8 + 2 * p;
        if (j < N) {
            float lo[4], hi[4];
#pragma unroll
            for (int q = 0; q < 4; q++) unpack2(acc[p][q], lo[q], hi[q]);
            *reinterpret_cast<float4*>(&G[((size_t)b * N + j) * N + k0 + tx * 4]) =
                make_float4(lo[0], lo[1], lo[2], lo[3]);
            *reinterpret_cast<float4*>(&G[((size_t)b * N + j + 1) * N + k0 + tx * 4]) =
                make_float4(hi[0], hi[1], hi[2], hi[3]);
        }
    }
}

// ---------------- e = G + G^T ; mask ; softmax over j ; *adj -----------------
constexpr int TKS = 16;
__global__ void __launch_bounds__(256)
k_softmax(const float* __restrict__ G2, const float* __restrict__ adj2, float* __restrict__ att2,
          const float* __restrict__ G1, const float* __restrict__ adj1, float* __restrict__ att1) {
    __shared__ float ecol[TKS * 513];
    int blk = blockIdx.x;
    const float *G, *adj; float* att; int N, b, k0;
    if (blk < 256) { N = 512; b = blk >> 5; k0 = (blk & 31) * TKS; G = G2; adj = adj2; att = att2; }
    else { int r = blk - 256; N = 64; b = r >> 2; k0 = (r & 3) * TKS; G = G1; adj = adj1; att = att1; }
    int t = threadIdx.x, lane = t & 31, w = t >> 5;
    size_t bN = (size_t)b * N;
    for (int idx = t; idx < N * TKS; idx += 256) {
        int j = idx >> 4, kk = idx & 15, k = k0 + kk;
        float g = G[(bN + j) * N + k] + G[(bN + k) * N + j];
        float a = adj[(bN + j) * N + k];
        ecol[kk * 513 + j] = (a > 0.f) ? g : -9e15f;
    }
    __syncthreads();
    for (int kk = w; kk < TKS; kk += 8) {
        float m = -INFINITY;
        for (int j = lane; j < N; j += 32) m = fmaxf(m, ecol[kk * 513 + j]);
#pragma unroll
        for (int o = 16; o; o >>= 1) m = fmaxf(m, __shfl_xor_sync(~0u, m, o));
        float s = 0.f;
        for (int j = lane; j < N; j += 32) {
            float e = expf(ecol[kk * 513 + j] - m);
            ecol[kk * 513 + j] = e; s += e;
        }
#pragma unroll
        for (int o = 16; o; o >>= 1) s += __shfl_xor_sync(~0u, s, o);
        float inv = 1.f / s;
        for (int j = lane; j < N; j += 32) {
            float a = adj[(bN + j) * N + k0 + kk];
            att[(bN + j) * N + k0 + kk] = ecol[kk * 513 + j] * inv * a;
        }
    }
}

// ---------------- hp = relu(att@h) ; gate  (merged, packed f32x2) ------------
constexpr int TMH = 16;
__global__ void __launch_bounds__(128)
k_hp_gate(const float* __restrict__ x2, const float* __restrict__ h2, const float* __restrict__ att2,
          const float* __restrict__ x1, const float* __restrict__ h1, const float* __restrict__ att1,
          const float* __restrict__ Wg, const float* __restrict__ bg,
          float* __restrict__ o2, float* __restrict__ o1) {
    __shared__ float attsT[512][TMH + 2];
    __shared__ float partial[TMH][4];
    __shared__ float coeff[TMH];
    int blk = blockIdx.x;
    const float *x, *hh, *att; float* out; int N, b, r0;
    if (blk < 256) { N = 512; b = blk >> 5; r0 = (blk & 31) * TMH; x = x2; hh = h2; att = att2; out = o2; }
    else { int r = blk - 256; N = 64; b = r >> 2; r0 = (r & 3) * TMH; x = x1; hh = h1; att = att1; out = o1; }
    int t = threadIdx.x, lane = t & 31, w = t >> 5;
    size_t bN = (size_t)b * N;
#pragma unroll
    for (int m = 0; m < TMH; m++)
        for (int j = t; j < N; j += 128) attsT[j][m] = att[(bN + r0 + m) * N + j];
    __syncthreads();
    unsigned long long acc[TMH / 2];
#pragma unroll
    for (int p = 0; p < TMH / 2; p++) acc[p] = 0ull;
    for (int j = 0; j < N; j++) {
        float hv = hh[(bN + j) * 128 + t];
        unsigned long long h2p = pack2(hv, hv);
#pragma unroll
        for (int p = 0; p < TMH / 2; p++) fma2(acc[p], lds2(&attsT[j][2 * p]), h2p);
    }
    float hp[TMH], xr[TMH];
#pragma unroll
    for (int p = 0; p < TMH / 2; p++) {
        float lo, hi; unpack2(acc[p], lo, hi);
        hp[2 * p] = fmaxf(lo, 0.f); hp[2 * p + 1] = fmaxf(hi, 0.f);
    }
    float wg0 = Wg[t], wg1 = Wg[128 + t];
#pragma unroll
    for (int m = 0; m < TMH; m++) {
        xr[m] = x[(bN + r0 + m) * 128 + t];
        float v = xr[m] * wg0 + hp[m] * wg1;
#pragma unroll
        for (int o = 16; o; o >>= 1) v += __shfl_down_sync(~0u, v, o);
        if (lane == 0) partial[m][w] = v;
    }
    __syncthreads();
    if (t < TMH)
        coeff[t] = sigmoidf(partial[t][0] + partial[t][1] + partial[t][2] + partial[t][3] + bg[0]);
    __syncthreads();
#pragma unroll
    for (int m = 0; m < TMH; m++) {
        float c = coeff[m];
        out[(bN + r0 + m) * 128 + t] = c * xr[m] + (1.f - c) * hp[m];
    }
}

// ---------------- distances --------------------------------------------------
__global__ void k_dm(const float* __restrict__ dmv, float* __restrict__ dm, int n) {
    int i = blockIdx.x * blockDim.x + threadIdx.x;
    if (i < n) {
        float xx = dmv[3 * (size_t)i + 0];
        float yy = dmv[3 * (size_t)i + 1];
        float zz = dmv[3 * (size_t)i + 2];
        float d = sqrtf(xx * xx + yy * yy + zz * zz + 1e-10f);
        dm[i] = (d < 0.5f) ? 1e10f : d;
    }
}

// ---------------- U precompute (merged, packed f32x2, TM=32) -----------------
constexpr int TMU = 32;
__global__ void __launch_bounds__(128)
k_precU(const float* __restrict__ x1e, const float* __restrict__ x2e,
        const float* __restrict__ WA1, const float* __restrict__ bA1,
        const float* __restrict__ WB1, const float* __restrict__ bB1,
        float* __restrict__ U1A, float* __restrict__ U1B,
        float* __restrict__ U2A, float* __restrict__ U2B) {
    constexpr int T1 = (B * N1) / TMU;      // 16
    int i = blockIdx.x % 7;
    int tile = blockIdx.x / 7;
    const float* x; float *UA, *UB; int r0, dOff; float biasMul;
    if (tile < T1) { x = x1e; UA = U1A; UB = U1B; r0 = tile * TMU; dOff = 0; biasMul = 1.f; }
    else { x = x2e; UA = U2A; UB = U2B; r0 = (tile - T1) * TMU; dOff = 128; biasMul = 0.f; }
    int hh = threadIdx.x;
    __shared__ float xsT[128][TMU + 2];
#pragma unroll
    for (int m = 0; m < TMU; m++) xsT[hh][m] = x[(size_t)(r0 + m) * 128 + hh];
    __syncthreads();
    float ba = bA1[i * 128 + hh] * biasMul, bb = bB1[i * 128 + hh] * biasMul;
    unsigned long long accA[TMU / 2], accB[TMU / 2];
#pragma unroll
    for (int p = 0; p < TMU / 2; p++) { accA[p] = pack2(ba, ba); accB[p] = pack2(bb, bb); }
    const float* wa = WA1 + ((size_t)i * 256 + dOff) * 128;
    const float* wb = WB1 + ((size_t)i * 256 + dOff) * 128;
    for (int d = 0; d < 128; d++) {
        float wav = wa[(size_t)d * 128 + hh], wbv = wb[(size_t)d * 128 + hh];
        unsigned long long w2a = pack2(wav, wav), w2b = pack2(wbv, wbv);
#pragma unroll
        for (int p = 0; p < TMU / 2; p++) {
            unsigned long long xs2 = lds2(&xsT[d][2 * p]);
            fma2(accA[p], xs2, w2a);
            fma2(accB[p], xs2, w2b);
        }
    }
#pragma unroll
    for (int p = 0; p < TMU / 2; p++) {
        float lo, hi;
        unpack2(accA[p], lo, hi);
        UA[((size_t)(r0 + 2 * p) * NT + i) * 128 + hh] = lo;
        UA[((size_t)(r0 + 2 * p + 1) * NT + i) * 128 + hh] = hi;
        unpack2(accB[p], lo, hi);
        UB[((size_t)(r0 + 2 * p) * NT + i) * 128 + hh] = lo;
        UB[((size_t)(r0 + 2 * p + 1) * NT + i) * 128 + hh] = hi;
    }
}

// ---------------- intercept ---------------------------------------------------
__global__ void k_intercept(const float* __restrict__ h1e, const float* __restrict__ valid,
                            const float* __restrict__ Wi1, const float* __restrict__ bi1,
                            const float* __restrict__ Wi2, const float* __restrict__ bi2,
                            float* __restrict__ out) {
    int b = blockIdx.x, t = threadIdx.x;
    int lane = t & 31, w = t >> 5;
    __shared__ float pooled[128];
    __shared__ float red[4];
    float p = 0.f;
    for (int j = 0; j < N1; j++)
        p = fmaf(h1e[((size_t)b * N1 + j) * 128 + t], valid[b * N1 + j], p);
    pooled[t] = p;
    __syncthreads();
    float acc = bi1[t];
    for (int d = 0; d < 128; d++) acc = fmaf(pooled[d], Wi1[d * 128 + t], acc);
    float v = fmaxf(acc, 0.f) * Wi2[t];
#pragma unroll
    for (int o = 16; o; o >>= 1) v += __shfl_down_sync(~0u, v, o);
    if (lane == 0) red[w] = v;
    __syncthreads();
    if (t == 0) {
        float s = red[0] + red[1] + red[2] + red[3] + bi2[0];
        s = 4.f * sigmoidf(s);
        float val = s / 7.f;
        for (int i = 0; i < NT; i++) out[b * NT + i] = val;
    }
}

// ---------------- sparse energies ---------------------------------------------
__global__ void k_energy(const float* __restrict__ U1A, const float* __restrict__ U1B,
                         const float* __restrict__ U2A, const float* __restrict__ U2B,
                         const float* __restrict__ WA2, const float* __restrict__ bA2,
                         const float* __restrict__ WB2, const float* __restrict__ bB2,
                         const float* __restrict__ Cc, const float* __restrict__ A_int,
                         const float* __restrict__ dm, float* __restrict__ epart) {
    int j = blockIdx.x % N1;
    int bi = blockIdx.x / N1;
    int i = bi % NT;
    int b = bi / NT;
    int t = threadIdx.x, lane = t & 31, w = t >> 5;
    __shared__ float u1a[128], u1b[128], wa2[128], wb2[128];
    __shared__ float part[4];
    u1a[t] = U1A[(((size_t)b * N1 + j) * NT + i) * 128 + t];
    u1b[t] = U1B[(((size_t)b * N1 + j) * NT + i) * 128 + t];
    wa2[t] = WA2[i * 128 + t];
    wb2[t] = WB2[i * 128 + t];
    __syncthreads();
    float bc = c_bconstraint[i];
    float bcinv = 1.f / (3.f * bc * bc);
    float Ci = Cc[i], ba2 = bA2[i], bb2 = bB2[i];
    const float* aint_row = A_int + (((size_t)b * NT + i) * N1 + j) * N2;
    const float* dm_row = dm + ((size_t)b * N1 + j) * N2;
    float esum = 0.f;
    for (int k = w; k < N2; k += 4) {
        float av = aint_row[k];
        if (av != 0.f) {
            const float* u2a = U2A + (((size_t)b * N2 + k) * NT + i) * 128;
            const float* u2b = U2B + (((size_t)b * N2 + k) * NT + i) * 128;
            float sA = 0.f, sB = 0.f;
#pragma unroll
            for (int q = 0; q < 4; q++) {
                int d = lane + 32 * q;
                sA = fmaf(fmaxf(u1a[d] + u2a[d], 0.f), wa2[d], sA);
                sB = fmaf(fmaxf(u1b[d] + u2b[d], 0.f), wb2[d], sB);
            }
#pragma unroll
            for (int o = 16; o; o >>= 1) {
                sA += __shfl_xor_sync(~0u, sA, o);
                sB += __shfl_xor_sync(~0u, sB, o);
            }
            if (lane == 0) {
                float Aa = 4.f * sigmoidf(sA + ba2);
                float Bp = sigmoidf(sB + bb2) * (2.f * bcinv) + bcinv;
                float dd = dm_row[k] - Ci;
                esum += Aa * (Bp * dd * dd - 1.f) * av;
            }
        }
    }
    if (lane == 0) part[w] = esum;
    __syncthreads();
    if (t == 0) epart[blockIdx.x] = part[0] + part[1] + part[2] + part[3];
}

// ---------------- deterministic reduce ----------------------------------------
__global__ void k_reduce(const float* __restrict__ epart, float* __restrict__ out) {
    int t = threadIdx.x;
    if (t < B * NT) {
        float s = 0.f;
        for (int j = 0; j < N1; j++) s += epart[(size_t)t * N1 + j];
        out[t] += s;
    }
}

// ---------------- orchestration ------------------------------------------------
extern "C" void kernel_launch(void* const* d_in, const int* in_sizes, int n_in,
                              void* d_out, int out_size) {
    const float* h1     = (const float*)d_in[0];
    const float* adj1   = (const float*)d_in[1];
    const float* h2     = (const float*)d_in[2];
    const float* adj2   = (const float*)d_in[3];
    const float* A_int  = (const float*)d_in[4];
    const float* dmv    = (const float*)d_in[5];
    const float* valid  = (const float*)d_in[6];
    const float* W_embed= (const float*)d_in[7];
    const float* gW     = (const float*)d_in[8];
    const float* gWb    = (const float*)d_in[9];
    const float* gA     = (const float*)d_in[10];
    const float* gGateW = (const float*)d_in[11];
    const float* gGateb = (const float*)d_in[12];
    const float* WA1    = (const float*)d_in[13];
    const float* bA1    = (const float*)d_in[14];
    const float* WA2    = (const float*)d_in[15];
    const float* bA2    = (const float*)d_in[16];
    const float* WB1    = (const float*)d_in[17];
    const float* bB1    = (const float*)d_in[18];
    const float* WB2    = (const float*)d_in[19];
    const float* bB2    = (const float*)d_in[20];
    const float* Cc     = (const float*)d_in[21];
    const float* Wi1    = (const float*)d_in[22];
    const float* bi1    = (const float*)d_in[23];
    const float* Wi2    = (const float*)d_in[24];
    const float* bi2    = (const float*)d_in[25];
    float* out = (float*)d_out;

    float* S = nullptr;
    cudaGetSymbolAddress((void**)&S, g_scratch);

    float* h1buf[2] = {S + OFF_H1A, S + OFF_H1B};
    float* h2buf[2] = {S + OFF_H2A, S + OFF_H2B};
    float* t1   = S + OFF_T1;
    float* ta1  = S + OFF_TA1;
    float* t2   = S + OFF_T2;
    float* ta2  = S + OFF_TA2;
    float* att1 = S + OFF_ATT1;
    float* att2 = S + OFF_ATT2;
    float* G1   = S + OFF_G1;
    float* G2   = S + OFF_G2;
    float* U1A  = S + OFF_U1A;
    float* U1B  = S + OFF_U1B;
    float* U2A  = S + OFF_U2A;
    float* U2B  = S + OFF_U2B;
    float* dmS  = S + OFF_DM;
    float* ep   = S + OFF_EP;

    // 1. embed (merged)
    k_embed<8><<<(B * N1 + B * N2) / 8, 128>>>(h1, h2, W_embed, h1buf[0], h2buf[0]);

    // 2. GAT layers (graph1 + graph2 merged per stage)
    int cur = 0;
    for (int l = 0; l < NL; l++) {
        const float* W  = gW + (size_t)l * D * D;
        const float* Wb = gWb + (size_t)l * D;
        const float* A  = gA + (size_t)l * D * D;
        const float* Gw = gGateW + (size_t)l * 2 * D;
        const float* Gb = gGateb + l;
        int nxt = cur ^ 1;
        k_h_hA<8><<<(B * N1 + B * N2) / 8, 128>>>(h1buf[cur], h2buf[cur], W, Wb, A,
                                                  t1, ta1, t2, ta2);
        k_gemmG<<<256 + 8, 256>>>(ta2, t2, G2, ta1, t1, G1);
        k_softmax<<<256 + 32, 256>>>(G2, adj2, att2, G1, adj1, att1);
        k_hp_gate<<<256 + 32, 128>>>(h2buf[cur], t2, att2, h1buf[cur], t1, att1,
                                     Gw, Gb, h2buf[nxt], h1buf[nxt]);
        cur = nxt;
    }
    const float* h1e = h1buf[cur];
    const float* h2e = h2buf[cur];

    // 3. factored MLP first layer (merged)
    k_precU<<<7 * ((B * N1 + B * N2) / TMU), 128>>>(h1e, h2e, WA1, bA1, WB1, bB1,
                                                    U1A, U1B, U2A, U2B);

    // 4. distances
    k_dm<<<(B * N1 * N2 + 255) / 256, 256>>>(dmv, dmS, B * N1 * N2);

    // 5. intercept (initializes out), sparse energies, deterministic reduce
    k_intercept<<<B, 128>>>(h1e, valid, Wi1, bi1, Wi2, bi2, out);
    k_energy<<<B * NT * N1, 128>>>(U1A, U1B, U2A, U2B, WA2, bA2, WB2, bB2,
                                   Cc, A_int, dmS, ep);
    k_reduce<<<1, 64>>>(ep, out);
}

// round 7
// speedup vs baseline: 2.3292x; 1.0687x over previous
#include <cuda_runtime.h>
#include <math.h>

constexpr int B = 8, N1 = 64, N2 = 512, D = 128, NL = 3, H = 128, NT = 7;

// ---------------- scratch (static device memory) ----------------------------
constexpr size_t SZ_H1   = (size_t)B * N1 * D;
constexpr size_t SZ_H2   = (size_t)B * N2 * D;
constexpr size_t SZ_ATT1 = (size_t)B * N1 * N1;
constexpr size_t SZ_ATT2 = (size_t)B * N2 * N2;
constexpr size_t SZ_U1   = (size_t)B * N1 * NT * H;
constexpr size_t SZ_U2   = (size_t)B * N2 * NT * H;
constexpr size_t SZ_EP   = (size_t)B * NT * N1;

constexpr size_t OFF_H1A  = 0;
constexpr size_t OFF_H1B  = OFF_H1A  + SZ_H1;
constexpr size_t OFF_H2A  = OFF_H1B  + SZ_H1;
constexpr size_t OFF_H2B  = OFF_H2A  + SZ_H2;
constexpr size_t OFF_T1   = OFF_H2B  + SZ_H2;
constexpr size_t OFF_TA1  = OFF_T1   + SZ_H1;
constexpr size_t OFF_T2   = OFF_TA1  + SZ_H1;
constexpr size_t OFF_TA2  = OFF_T2   + SZ_H2;
constexpr size_t OFF_ATT1 = OFF_TA2  + SZ_H2;
constexpr size_t OFF_ATT2 = OFF_ATT1 + SZ_ATT1;
constexpr size_t OFF_G1   = OFF_ATT2 + SZ_ATT2;
constexpr size_t OFF_G2   = OFF_G1   + SZ_ATT1;
constexpr size_t OFF_E1   = OFF_G2   + SZ_ATT2;
constexpr size_t OFF_E2   = OFF_E1   + SZ_ATT1;
constexpr size_t OFF_U1A  = OFF_E2   + SZ_ATT2;
constexpr size_t OFF_U1B  = OFF_U1A  + SZ_U1;
constexpr size_t OFF_U2A  = OFF_U1B  + SZ_U1;
constexpr size_t OFF_U2B  = OFF_U2A  + SZ_U2;
constexpr size_t OFF_EP   = OFF_U2B  + SZ_U2;
constexpr size_t SCRATCH_TOTAL = OFF_EP + SZ_EP;

__device__ float g_scratch[SCRATCH_TOTAL];

__constant__ float c_bconstraint[NT] = {1.159f, 0.448f, 0.927f, 0.902f, 0.349f, 0.789f, 0.198f};

__device__ __forceinline__ float sigmoidf(float x) { return 1.f / (1.f + expf(-x)); }

// ---------------- packed fp32x2 helpers (sm_103a dual-fp32 pipe) ------------
__device__ __forceinline__ unsigned long long pack2(float lo, float hi) {
    unsigned long long r;
    asm("mov.b64 %0, {%1,%2};" : "=l"(r) : "f"(lo), "f"(hi));
    return r;
}
__device__ __forceinline__ void unpack2(unsigned long long v, float& lo, float& hi) {
    asm("mov.b64 {%0,%1}, %2;" : "=f"(lo), "=f"(hi) : "l"(v));
}
__device__ __forceinline__ void fma2(unsigned long long& d, unsigned long long a,
                                     unsigned long long b) {
    asm("fma.rn.f32x2 %0, %1, %2, %0;" : "+l"(d) : "l"(a), "l"(b));
}
__device__ __forceinline__ unsigned long long lds2(const float* p) {
    return *reinterpret_cast<const unsigned long long*>(p);
}

// ---------------- embedding (both graphs, one launch) ------------------------
template <int TM>
__global__ void k_embed(const float* __restrict__ x1, const float* __restrict__ x2,
                        const float* __restrict__ W,
                        float* __restrict__ o1, float* __restrict__ o2) {
    constexpr int T1 = (B * N1) / TM;
    int blk = blockIdx.x;
    const float* x; float* out; int r0;
    if (blk < T1) { x = x1; out = o1; r0 = blk * TM; }
    else          { x = x2; out = o2; r0 = (blk - T1) * TM; }
    int t = threadIdx.x;
    __shared__ float xs[TM][56];
    for (int idx = t; idx < TM * 56; idx += 128) {
        int m = idx / 56, d = idx % 56;
        xs[m][d] = x[(size_t)(r0 + m) * 56 + d];
    }
    __syncthreads();
    float acc[TM];
#pragma unroll
    for (int m = 0; m < TM; m++) acc[m] = 0.f;
    for (int k = 0; k < 56; k++) {
        float wv = W[k * 128 + t];
#pragma unroll
        for (int m = 0; m < TM; m++) acc[m] = fmaf(xs[m][k], wv, acc[m]);
    }
#pragma unroll
    for (int m = 0; m < TM; m++) out[(size_t)(r0 + m) * 128 + t] = acc[m];
}

// ---------------- h = x@W + Wb ; hA = h@A  (merged, packed f32x2) ------------
template <int TM>   // TM must be even
__global__ void __launch_bounds__(128)
k_h_hA(const float* __restrict__ x1, const float* __restrict__ x2,
       const float* __restrict__ W, const float* __restrict__ Wb,
       const float* __restrict__ A,
       float* __restrict__ h1o, float* __restrict__ hA1o,
       float* __restrict__ h2o, float* __restrict__ hA2o) {
    constexpr int T1 = (B * N1) / TM;
    int blk = blockIdx.x;
    const float* x; float *ho, *hAo; int r0;
    if (blk < T1) { x = x1; ho = h1o; hAo = hA1o; r0 = blk * TM; }
    else          { x = x2; ho = h2o; hAo = hA2o; r0 = (blk - T1) * TM; }
    int t = threadIdx.x;
    __shared__ float xsT[128][TM + 2];
    __shared__ float hsT[128][TM + 2];
#pragma unroll
    for (int m = 0; m < TM; m++) xsT[t][m] = x[(size_t)(r0 + m) * 128 + t];
    __syncthreads();
    unsigned long long acc[TM / 2];
    float wb = Wb[t];
#pragma unroll
    for (int p = 0; p < TM / 2; p++) acc[p] = pack2(wb, wb);
    for (int k = 0; k < 128; k++) {
        float wv = W[k * 128 + t];
        unsigned long long w2 = pack2(wv, wv);
#pragma unroll
        for (int p = 0; p < TM / 2; p++) fma2(acc[p], lds2(&xsT[k][2 * p]), w2);
    }
#pragma unroll
    for (int p = 0; p < TM / 2; p++) {
        float lo, hi; unpack2(acc[p], lo, hi);
        ho[(size_t)(r0 + 2 * p) * 128 + t] = lo;
        ho[(size_t)(r0 + 2 * p + 1) * 128 + t] = hi;
        hsT[t][2 * p] = lo; hsT[t][2 * p + 1] = hi;
    }
    __syncthreads();
#pragma unroll
    for (int p = 0; p < TM / 2; p++) acc[p] = 0ull;
    for (int k = 0; k < 128; k++) {
        float av = A[k * 128 + t];
        unsigned long long a2 = pack2(av, av);
#pragma unroll
        for (int p = 0; p < TM / 2; p++) fma2(acc[p], lds2(&hsT[k][2 * p]), a2);
    }
#pragma unroll
    for (int p = 0; p < TM / 2; p++) {
        float lo, hi; unpack2(acc[p], lo, hi);
        hAo[(size_t)(r0 + 2 * p) * 128 + t] = lo;
        hAo[(size_t)(r0 + 2 * p + 1) * 128 + t] = hi;
    }
}

// ---------------- G = hA @ h^T  (register-tiled GEMM, both graphs) -----------
constexpr int BJ = 128, BK = 64, DKK = 16;
__global__ void __launch_bounds__(256)
k_gemmG(const float* __restrict__ hA2, const float* __restrict__ h2, float* __restrict__ G2,
        const float* __restrict__ hA1, const float* __restrict__ h1, float* __restrict__ G1) {
    int blk = blockIdx.x;
    const float *hA, *hh; float* G; int N, b, j0, k0;
    if (blk < 256) { N = 512; b = blk >> 5; j0 = ((blk >> 3) & 3) * BJ; k0 = (blk & 7) * BK;
                     hA = hA2; hh = h2; G = G2; }
    else           { N = 64; b = blk - 256; j0 = 0; k0 = 0; hA = hA1; hh = h1; G = G1; }
    int t = threadIdx.x;
    int tx = t & 15, ty = t >> 4;
    __shared__ float As[DKK][BJ + 4];
    __shared__ float Bs[DKK][BK + 4];
    unsigned long long acc[4][4];
#pragma unroll
    for (int p = 0; p < 4; p++)
#pragma unroll
        for (int q = 0; q < 4; q++) acc[p][q] = 0ull;

    for (int dc = 0; dc < 128; dc += DKK) {
#pragma unroll
        for (int i = 0; i < 2; i++) {
            int idx = t + i * 256;
            int jrow = idx >> 2, dq = idx & 3;
            float4 v;
            if (j0 + jrow < N)
                v = *reinterpret_cast<const float4*>(&hA[((size_t)b * N + j0 + jrow) * 128 + dc + dq * 4]);
            else v = make_float4(0.f, 0.f, 0.f, 0.f);
            As[dq * 4 + 0][jrow] = v.x; As[dq * 4 + 1][jrow] = v.y;
            As[dq * 4 + 2][jrow] = v.z; As[dq * 4 + 3][jrow] = v.w;
        }
        {
            int krow = t >> 2, dq = t & 3;
            float4 v = *reinterpret_cast<const float4*>(&hh[((size_t)b * N + k0 + krow) * 128 + dc + dq * 4]);
            Bs[dq * 4 + 0][krow] = v.x; Bs[dq * 4 + 1][krow] = v.y;
            Bs[dq * 4 + 2][krow] = v.z; Bs[dq * 4 + 3][krow] = v.w;
        }
        __syncthreads();
#pragma unroll
        for (int d = 0; d < DKK; d++) {
            unsigned long long a2[4];
#pragma unroll
            for (int p = 0; p < 4; p++) a2[p] = lds2(&As[d][ty * 8 + 2 * p]);
            float4 bv = *reinterpret_cast<const float4*>(&Bs[d][tx * 4]);
            unsigned long long b2[4] = {pack2(bv.x, bv.x), pack2(bv.y, bv.y),
                                        pack2(bv.z, bv.z), pack2(bv.w, bv.w)};
#pragma unroll
            for (int p = 0; p < 4; p++)
#pragma unroll
                for (int q = 0; q < 4; q++) fma2(acc[p][q], a2[p], b2[q]);
        }
        __syncthreads();
    }
#pragma unroll
    for (int p = 0; p < 4; p++) {
        int j = j0 + ty * 8 + 2 * p;
        if (j < N) {
            float lo[4], hi[4];
#pragma unroll
            for (int q = 0; q < 4; q++) unpack2(acc[p][q], lo[q], hi[q]);
            *reinterpret_cast<float4*>(&G[((size_t)b * N + j) * N + k0 + tx * 4]) =
                make_float4(lo[0], lo[1], lo[2], lo[3]);
            *reinterpret_cast<float4*>(&G[((size_t)b * N + j + 1) * N + k0 + tx * 4]) =
                make_float4(hi[0], hi[1], hi[2], hi[3]);
        }
    }
}

// ---------------- E[j,k] = adj>0 ? G[j,k]+G[k,j] : -1e30  (all coalesced) ----
constexpr int TS = 64;
__global__ void __launch_bounds__(256)
k_symmask(const float* __restrict__ G2, const float* __restrict__ adj2, float* __restrict__ E2,
          const float* __restrict__ G1, const float* __restrict__ adj1, float* __restrict__ E1) {
    int blk = blockIdx.x;
    const float *G, *adj; float* E; int N, b, j0, k0;
    if (blk < 512) { N = 512; b = blk >> 6; j0 = ((blk >> 3) & 7) * TS; k0 = (blk & 7) * TS;
                     G = G2; adj = adj2; E = E2; }
    else           { N = 64; b = blk - 512; j0 = 0; k0 = 0; G = G1; adj = adj1; E = E1; }
    __shared__ float Bs[TS][TS + 1];
    int t = threadIdx.x;
    size_t bNN = (size_t)b * N * N;
    for (int idx = t; idx < TS * TS; idx += 256) {
        int r = idx >> 6, c = idx & 63;
        Bs[r][c] = G[bNN + (size_t)(k0 + r) * N + j0 + c];
    }
    __syncthreads();
    for (int idx = t; idx < TS * TS; idx += 256) {
        int r = idx >> 6, c = idx & 63;
        size_t off = bNN + (size_t)(j0 + r) * N + k0 + c;
        float a = adj[off];
        E[off] = (a > 0.f) ? (G[off] + Bs[c][r]) : -1e30f;
    }
}

// ---------------- column softmax over axis-0, coalesced row-marching ---------
// att[j,k] = exp(E[j,k]-M_k)/S_k ; masked entries underflow to exactly 0, and
// adj in {0,1} makes the trailing *adj an identity.
constexpr int CS = 32;
__global__ void __launch_bounds__(256)
k_colsoftmax(const float* __restrict__ E2, float* __restrict__ att2,
             const float* __restrict__ E1, float* __restrict__ att1) {
    int blk = blockIdx.x;
    const float* E; float* att; int N, b, k0;
    if (blk < 128) { N = 512; b = blk >> 4; k0 = (blk & 15) * CS; E = E2; att = att2; }
    else { int r = blk - 128; N = 64; b = r >> 1; k0 = (r & 1) * CS; E = E1; att = att1; }
    int t = threadIdx.x, c = t & 31, rg = t >> 5;       // 8 row-groups
    size_t base = (size_t)b * N * N + k0 + c;
    float m = -INFINITY, s = 0.f;
    for (int j = rg; j < N; j += 8) {
        float v = E[base + (size_t)j * N];
        float mn = fmaxf(m, v);
        s = s * expf(m - mn) + expf(v - mn);
        m = mn;
    }
    __shared__ float ms[8][33], ss[8][33];
    ms[rg][c] = m; ss[rg][c] = s;
    __syncthreads();
    if (rg == 0) {
        float M = ms[0][c];
#pragma unroll
        for (int r = 1; r < 8; r++) M = fmaxf(M, ms[r][c]);
        float S = 0.f;
#pragma unroll
        for (int r = 0; r < 8; r++) S += ss[r][c] * expf(ms[r][c] - M);
        ms[0][c] = M; ss[0][c] = 1.f / S;
    }
    __syncthreads();
    float M = ms[0][c], inv = ss[0][c];
    for (int j = rg; j < N; j += 8) {
        float v = E[base + (size_t)j * N];
        att[base + (size_t)j * N] = expf(v - M) * inv;
    }
}

// ---------------- hp = relu(att@h) ; gate  (merged, packed f32x2) ------------
constexpr int TMH = 16;
__global__ void __launch_bounds__(128)
k_hp_gate(const float* __restrict__ x2, const float* __restrict__ h2, const float* __restrict__ att2,
          const float* __restrict__ x1, const float* __restrict__ h1, const float* __restrict__ att1,
          const float* __restrict__ Wg, const float* __restrict__ bg,
          float* __restrict__ o2, float* __restrict__ o1) {
    __shared__ float attsT[512][TMH + 2];   // even row stride -> 8B-aligned lds2
    __shared__ float partial[TMH][4];
    __shared__ float coeff[TMH];
    int blk = blockIdx.x;
    const float *x, *hh, *att; float* out; int N, b, r0;
    if (blk < 256) { N = 512; b = blk >> 5; r0 = (blk & 31) * TMH; x = x2; hh = h2; att = att2; out = o2; }
    else { int r = blk - 256; N = 64; b = r >> 2; r0 = (r & 3) * TMH; x = x1; hh = h1; att = att1; out = o1; }
    int t = threadIdx.x, lane = t & 31, w = t >> 5;
    size_t bN = (size_t)b * N;
#pragma unroll
    for (int m = 0; m < TMH; m++)
        for (int j = t; j < N; j += 128) attsT[j][m] = att[(bN + r0 + m) * N + j];
    __syncthreads();
    unsigned long long acc[TMH / 2];
#pragma unroll
    for (int p = 0; p < TMH / 2; p++) acc[p] = 0ull;
    for (int j = 0; j < N; j++) {
        float hv = hh[(bN + j) * 128 + t];
        unsigned long long h2p = pack2(hv, hv);
#pragma unroll
        for (int p = 0; p < TMH / 2; p++) fma2(acc[p], lds2(&attsT[j][2 * p]), h2p);
    }
    float hp[TMH], xr[TMH];
#pragma unroll
    for (int p = 0; p < TMH / 2; p++) {
        float lo, hi; unpack2(acc[p], lo, hi);
        hp[2 * p] = fmaxf(lo, 0.f); hp[2 * p + 1] = fmaxf(hi, 0.f);
    }
    float wg0 = Wg[t], wg1 = Wg[128 + t];
#pragma unroll
    for (int m = 0; m < TMH; m++) {
        xr[m] = x[(bN + r0 + m) * 128 + t];
        float v = xr[m] * wg0 + hp[m] * wg1;
#pragma unroll
        for (int o = 16; o; o >>= 1) v += __shfl_down_sync(~0u, v, o);
        if (lane == 0) partial[m][w] = v;
    }
    __syncthreads();
    if (t < TMH)
        coeff[t] = sigmoidf(partial[t][0] + partial[t][1] + partial[t][2] + partial[t][3] + bg[0]);
    __syncthreads();
#pragma unroll
    for (int m = 0; m < TMH; m++) {
        float c = coeff[m];
        out[(bN + r0 + m) * 128 + t] = c * xr[m] + (1.f - c) * hp[m];
    }
}

// ---------------- U precompute (merged, packed f32x2, TM=32) -----------------
constexpr int TMU = 32;
__global__ void __launch_bounds__(128)
k_precU(const float* __restrict__ x1e, const float* __restrict__ x2e,
        const float* __restrict__ WA1, const float* __restrict__ bA1,
        const float* __restrict__ WB1, const float* __restrict__ bB1,
        float* __restrict__ U1A, float* __restrict__ U1B,
        float* __restrict__ U2A, float* __restrict__ U2B) {
    constexpr int T1 = (B * N1) / TMU;      // 16
    int i = blockIdx.x % 7;
    int tile = blockIdx.x / 7;
    const float* x; float *UA, *UB; int r0, dOff; float biasMul;
    if (tile < T1) { x = x1e; UA = U1A; UB = U1B; r0 = tile * TMU; dOff = 0; biasMul = 1.f; }
    else { x = x2e; UA = U2A; UB = U2B; r0 = (tile - T1) * TMU; dOff = 128; biasMul = 0.f; }
    int hh = threadIdx.x;
    __shared__ float xsT[128][TMU + 2];
#pragma unroll
    for (int m = 0; m < TMU; m++) xsT[hh][m] = x[(size_t)(r0 + m) * 128 + hh];
    __syncthreads();
    float ba = bA1[i * 128 + hh] * biasMul, bb = bB1[i * 128 + hh] * biasMul;
    unsigned long long accA[TMU / 2], accB[TMU / 2];
#pragma unroll
    for (int p = 0; p < TMU / 2; p++) { accA[p] = pack2(ba, ba); accB[p] = pack2(bb, bb); }
    const float* wa = WA1 + ((size_t)i * 256 + dOff) * 128;
    const float* wb = WB1 + ((size_t)i * 256 + dOff) * 128;
    for (int d = 0; d < 128; d++) {
        float wav = wa[(size_t)d * 128 + hh], wbv = wb[(size_t)d * 128 + hh];
        unsigned long long w2a = pack2(wav, wav), w2b = pack2(wbv, wbv);
#pragma unroll
        for (int p = 0; p < TMU / 2; p++) {
            unsigned long long xs2 = lds2(&xsT[d][2 * p]);
            fma2(accA[p], xs2, w2a);
            fma2(accB[p], xs2, w2b);
        }
    }
#pragma unroll
    for (int p = 0; p < TMU / 2; p++) {
        float lo, hi;
        unpack2(accA[p], lo, hi);
        UA[((size_t)(r0 + 2 * p) * NT + i) * 128 + hh] = lo;
        UA[((size_t)(r0 + 2 * p + 1) * NT + i) * 128 + hh] = hi;
        unpack2(accB[p], lo, hi);
        UB[((size_t)(r0 + 2 * p) * NT + i) * 128 + hh] = lo;
        UB[((size_t)(r0 + 2 * p + 1) * NT + i) * 128 + hh] = hi;
    }
}

// ---------------- intercept ---------------------------------------------------
__global__ void k_intercept(const float* __restrict__ h1e, const float* __restrict__ valid,
                            const float* __restrict__ Wi1, const float* __restrict__ bi1,
                            const float* __restrict__ Wi2, const float* __restrict__ bi2,
                            float* __restrict__ out) {
    int b = blockIdx.x, t = threadIdx.x;
    int lane = t & 31, w = t >> 5;
    __shared__ float pooled[128];
    __shared__ float red[4];
    float p = 0.f;
    for (int j = 0; j < N1; j++)
        p = fmaf(h1e[((size_t)b * N1 + j) * 128 + t], valid[b * N1 + j], p);
    pooled[t] = p;
    __syncthreads();
    float acc = bi1[t];
    for (int d = 0; d < 128; d++) acc = fmaf(pooled[d], Wi1[d * 128 + t], acc);
    float v = fmaxf(acc, 0.f) * Wi2[t];
#pragma unroll
    for (int o = 16; o; o >>= 1) v += __shfl_down_sync(~0u, v, o);
    if (lane == 0) red[w] = v;
    __syncthreads();
    if (t == 0) {
        float s = red[0] + red[1] + red[2] + red[3] + bi2[0];
        s = 4.f * sigmoidf(s);
        float val = s / 7.f;
        for (int i = 0; i < NT; i++) out[b * NT + i] = val;
    }
}

// ---------------- sparse energies (dm computed inline from dmv) ---------------
__global__ void k_energy(const float* __restrict__ U1A, const float* __restrict__ U1B,
                         const float* __restrict__ U2A, const float* __restrict__ U2B,
                         const float* __restrict__ WA2, const float* __restrict__ bA2,
                         const float* __restrict__ WB2, const float* __restrict__ bB2,
                         const float* __restrict__ Cc, const float* __restrict__ A_int,
                         const float* __restrict__ dmv, float* __restrict__ epart) {
    int j = blockIdx.x % N1;
    int bi = blockIdx.x / N1;
    int i = bi % NT;
    int b = bi / NT;
    int t = threadIdx.x, lane = t & 31, w = t >> 5;
    __shared__ float u1a[128], u1b[128], wa2[128], wb2[128];
    __shared__ float part[4];
    u1a[t] = U1A[(((size_t)b * N1 + j) * NT + i) * 128 + t];
    u1b[t] = U1B[(((size_t)b * N1 + j) * NT + i) * 128 + t];
    wa2[t] = WA2[i * 128 + t];
    wb2[t] = WB2[i * 128 + t];
    __syncthreads();
    float bc = c_bconstraint[i];
    float bcinv = 1.f / (3.f * bc * bc);
    float Ci = Cc[i], ba2 = bA2[i], bb2 = bB2[i];
    const float* aint_row = A_int + (((size_t)b * NT + i) * N1 + j) * N2;
    const float* dmv_row = dmv + ((size_t)b * N1 + j) * N2 * 3;
    float esum = 0.f;
    for (int k = w; k < N2; k += 4) {
        float av = aint_row[k];
        if (av != 0.f) {
            const float* u2a = U2A + (((size_t)b * N2 + k) * NT + i) * 128;
            const float* u2b = U2B + (((size_t)b * N2 + k) * NT + i) * 128;
            float sA = 0.f, sB = 0.f;
#pragma unroll
            for (int q = 0; q < 4; q++) {
                int d = lane + 32 * q;
                sA = fmaf(fmaxf(u1a[d] + u2a[d], 0.f), wa2[d], sA);
                sB = fmaf(fmaxf(u1b[d] + u2b[d], 0.f), wb2[d], sB);
            }
#pragma unroll
            for (int o = 16; o; o >>= 1) {
                sA += __shfl_xor_sync(~0u, sA, o);
                sB += __shfl_xor_sync(~0u, sB, o);
            }
            if (lane == 0) {
                float xx = dmv_row[3 * k + 0];
                float yy = dmv_row[3 * k + 1];
                float zz = dmv_row[3 * k + 2];
                float dmval = sqrtf(xx * xx + yy * yy + zz * zz + 1e-10f);
                dmval = (dmval < 0.5f) ? 1e10f : dmval;
                float Aa = 4.f * sigmoidf(sA + ba2);
                float Bp = sigmoidf(sB + bb2) * (2.f * bcinv) + bcinv;
                float dd = dmval - Ci;
                esum += Aa * (Bp * dd * dd - 1.f) * av;
            }
        }
    }
    if (lane == 0) part[w] = esum;
    __syncthreads();
    if (t == 0) epart[blockIdx.x] = part[0] + part[1] + part[2] + part[3];
}

// ---------------- deterministic reduce ----------------------------------------
__global__ void k_reduce(const float* __restrict__ epart, float* __restrict__ out) {
    int t = threadIdx.x;
    if (t < B * NT) {
        float s = 0.f;
        for (int j = 0; j < N1; j++) s += epart[(size_t)t * N1 + j];
        out[t] += s;
    }
}

// ---------------- orchestration ------------------------------------------------
extern "C" void kernel_launch(void* const* d_in, const int* in_sizes, int n_in,
                              void* d_out, int out_size) {
    const float* h1     = (const float*)d_in[0];
    const float* adj1   = (const float*)d_in[1];
    const float* h2     = (const float*)d_in[2];
    const float* adj2   = (const float*)d_in[3];
    const float* A_int  = (const float*)d_in[4];
    const float* dmv    = (const float*)d_in[5];
    const float* valid  = (const float*)d_in[6];
    const float* W_embed= (const float*)d_in[7];
    const float* gW     = (const float*)d_in[8];
    const float* gWb    = (const float*)d_in[9];
    const float* gA     = (const float*)d_in[10];
    const float* gGateW = (const float*)d_in[11];
    const float* gGateb = (const float*)d_in[12];
    const float* WA1    = (const float*)d_in[13];
    const float* bA1    = (const float*)d_in[14];
    const float* WA2    = (const float*)d_in[15];
    const float* bA2    = (const float*)d_in[16];
    const float* WB1    = (const float*)d_in[17];
    const float* bB1    = (const float*)d_in[18];
    const float* WB2    = (const float*)d_in[19];
    const float* bB2    = (const float*)d_in[20];
    const float* Cc     = (const float*)d_in[21];
    const float* Wi1    = (const float*)d_in[22];
    const float* bi1    = (const float*)d_in[23];
    const float* Wi2    = (const float*)d_in[24];
    const float* bi2    = (const float*)d_in[25];
    float* out = (float*)d_out;

    float* S = nullptr;
    cudaGetSymbolAddress((void**)&S, g_scratch);

    float* h1buf[2] = {S + OFF_H1A, S + OFF_H1B};
    float* h2buf[2] = {S + OFF_H2A, S + OFF_H2B};
    float* t1   = S + OFF_T1;
    float* ta1  = S + OFF_TA1;
    float* t2   = S + OFF_T2;
    float* ta2  = S + OFF_TA2;
    float* att1 = S + OFF_ATT1;
    float* att2 = S + OFF_ATT2;
    float* G1   = S + OFF_G1;
    float* G2   = S + OFF_G2;
    float* E1   = S + OFF_E1;
    float* E2   = S + OFF_E2;
    float* U1A  = S + OFF_U1A;
    float* U1B  = S + OFF_U1B;
    float* U2A  = S + OFF_U2A;
    float* U2B  = S + OFF_U2B;
    float* ep   = S + OFF_EP;

    // 1. embed (merged)
    k_embed<8><<<(B * N1 + B * N2) / 8, 128>>>(h1, h2, W_embed, h1buf[0], h2buf[0]);

    // 2. GAT layers (graph1 + graph2 merged per stage)
    int cur = 0;
    for (int l = 0; l < NL; l++) {
        const float* W  = gW + (size_t)l * D * D;
        const float* Wb = gWb + (size_t)l * D;
        const float* A  = gA + (size_t)l * D * D;
        const float* Gw = gGateW + (size_t)l * 2 * D;
        const float* Gb = gGateb + l;
        int nxt = cur ^ 1;
        k_h_hA<8><<<(B * N1 + B * N2) / 8, 128>>>(h1buf[cur], h2buf[cur], W, Wb, A,
                                                  t1, ta1, t2, ta2);
        k_gemmG<<<256 + 8, 256>>>(ta2, t2, G2, ta1, t1, G1);
        k_symmask<<<512 + 8, 256>>>(G2, adj2, E2, G1, adj1, E1);
        k_colsoftmax<<<128 + 16, 256>>>(E2, att2, E1, att1);
        k_hp_gate<<<256 + 32, 128>>>(h2buf[cur], t2, att2, h1buf[cur], t1, att1,
                                     Gw, Gb, h2buf[nxt], h1buf[nxt]);
        cur = nxt;
    }
    const float* h1e = h1buf[cur];
    const float* h2e = h2buf[cur];

    // 3. factored MLP first layer (merged)
    k_precU<<<7 * ((B * N1 + B * N2) / TMU), 128>>>(h1e, h2e, WA1, bA1, WB1, bB1,
                                                    U1A, U1B, U2A, U2B);

    // 4. intercept (initializes out), sparse energies (dm inline), reduce
    k_intercept<<<B, 128>>>(h1e, valid, Wi1, bi1, Wi2, bi2, out);
    k_energy<<<B * NT * N1, 128>>>(U1A, U1B, U2A, U2B, WA2, bA2, WB2, bB2,
                                   Cc, A_int, dmv, ep);
    k_reduce<<<1, 64>>>(ep, out);
}

// round 9
// speedup vs baseline: 2.4203x; 1.0391x over previous
#include <cuda_runtime.h>
#include <math.h>

constexpr int B = 8, N1 = 64, N2 = 512, D = 128, NL = 3, H = 128, NT = 7;

// ---------------- scratch (static device memory) ----------------------------
constexpr size_t SZ_H1   = (size_t)B * N1 * D;
constexpr size_t SZ_H2   = (size_t)B * N2 * D;
constexpr size_t SZ_ATT1 = (size_t)B * N1 * N1;
constexpr size_t SZ_ATT2 = (size_t)B * N2 * N2;
constexpr size_t SZ_U1   = (size_t)B * N1 * NT * H;
constexpr size_t SZ_U2   = (size_t)B * N2 * NT * H;
constexpr size_t SZ_EP   = (size_t)B * NT * N1;

constexpr size_t OFF_H1A  = 0;
constexpr size_t OFF_H1B  = OFF_H1A  + SZ_H1;
constexpr size_t OFF_H2A  = OFF_H1B  + SZ_H1;
constexpr size_t OFF_H2B  = OFF_H2A  + SZ_H2;
constexpr size_t OFF_T1   = OFF_H2B  + SZ_H2;
constexpr size_t OFF_TA1  = OFF_T1   + SZ_H1;
constexpr size_t OFF_T2   = OFF_TA1  + SZ_H1;
constexpr size_t OFF_TA2  = OFF_T2   + SZ_H2;
constexpr size_t OFF_ATT1 = OFF_TA2  + SZ_H2;
constexpr size_t OFF_ATT2 = OFF_ATT1 + SZ_ATT1;
constexpr size_t OFF_E1   = OFF_ATT2 + SZ_ATT2;
constexpr size_t OFF_E2   = OFF_E1   + SZ_ATT1;
constexpr size_t OFF_U1A  = OFF_E2   + SZ_ATT2;
constexpr size_t OFF_U1B  = OFF_U1A  + SZ_U1;
constexpr size_t OFF_U2A  = OFF_U1B  + SZ_U1;
constexpr size_t OFF_U2B  = OFF_U2A  + SZ_U2;
constexpr size_t OFF_EP   = OFF_U2B  + SZ_U2;
constexpr size_t SCRATCH_TOTAL = OFF_EP + SZ_EP;

__device__ float g_scratch[SCRATCH_TOTAL];

__constant__ float c_bconstraint[NT] = {1.159f, 0.448f, 0.927f, 0.902f, 0.349f, 0.789f, 0.198f};

__device__ __forceinline__ float sigmoidf(float x) { return 1.f / (1.f + expf(-x)); }

// ---------------- packed fp32x2 helpers (sm_103a dual-fp32 pipe) ------------
__device__ __forceinline__ unsigned long long pack2(float lo, float hi) {
    unsigned long long r;
    asm("mov.b64 %0, {%1,%2};" : "=l"(r) : "f"(lo), "f"(hi));
    return r;
}
__device__ __forceinline__ void unpack2(unsigned long long v, float& lo, float& hi) {
    asm("mov.b64 {%0,%1}, %2;" : "=f"(lo), "=f"(hi) : "l"(v));
}
__device__ __forceinline__ void fma2(unsigned long long& d, unsigned long long a,
                                     unsigned long long b) {
    asm("fma.rn.f32x2 %0, %1, %2, %0;" : "+l"(d) : "l"(a), "l"(b));
}
__device__ __forceinline__ unsigned long long lds2(const float* p) {
    return *reinterpret_cast<const unsigned long long*>(p);
}

// ---------------- embedding (both graphs, one launch) ------------------------
template <int TM>
__global__ void k_embed(const float* __restrict__ x1, const float* __restrict__ x2,
                        const float* __restrict__ W,
                        float* __restrict__ o1, float* __restrict__ o2) {
    constexpr int T1 = (B * N1) / TM;
    int blk = blockIdx.x;
    const float* x; float* out; int r0;
    if (blk < T1) { x = x1; out = o1; r0 = blk * TM; }
    else          { x = x2; out = o2; r0 = (blk - T1) * TM; }
    int t = threadIdx.x;
    __shared__ float xs[TM][56];
    for (int idx = t; idx < TM * 56; idx += 128) {
        int m = idx / 56, d = idx % 56;
        xs[m][d] = x[(size_t)(r0 + m) * 56 + d];
    }
    __syncthreads();
    float acc[TM];
#pragma unroll
    for (int m = 0; m < TM; m++) acc[m] = 0.f;
    for (int k = 0; k < 56; k++) {
        float wv = W[k * 128 + t];
#pragma unroll
        for (int m = 0; m < TM; m++) acc[m] = fmaf(xs[m][k], wv, acc[m]);
    }
#pragma unroll
    for (int m = 0; m < TM; m++) out[(size_t)(r0 + m) * 128 + t] = acc[m];
}

// ---------------- h = x@W + Wb ; hA = h@A  (merged, packed f32x2) ------------
template <int TM>   // TM must be even
__global__ void __launch_bounds__(128)
k_h_hA(const float* __restrict__ x1, const float* __restrict__ x2,
       const float* __restrict__ W, const float* __restrict__ Wb,
       const float* __restrict__ A,
       float* __restrict__ h1o, float* __restrict__ hA1o,
       float* __restrict__ h2o, float* __restrict__ hA2o) {
    constexpr int T1 = (B * N1) / TM;
    int blk = blockIdx.x;
    const float* x; float *ho, *hAo; int r0;
    if (blk < T1) { x = x1; ho = h1o; hAo = hA1o; r0 = blk * TM; }
    else          { x = x2; ho = h2o; hAo = hA2o; r0 = (blk - T1) * TM; }
    int t = threadIdx.x;
    __shared__ float xsT[128][TM + 2];
    __shared__ float hsT[128][TM + 2];
#pragma unroll
    for (int m = 0; m < TM; m++) xsT[t][m] = x[(size_t)(r0 + m) * 128 + t];
    __syncthreads();
    unsigned long long acc[TM / 2];
    float wb = Wb[t];
#pragma unroll
    for (int p = 0; p < TM / 2; p++) acc[p] = pack2(wb, wb);
    for (int k = 0; k < 128; k++) {
        float wv = W[k * 128 + t];
        unsigned long long w2 = pack2(wv, wv);
#pragma unroll
        for (int p = 0; p < TM / 2; p++) fma2(acc[p], lds2(&xsT[k][2 * p]), w2);
    }
#pragma unroll
    for (int p = 0; p < TM / 2; p++) {
        float lo, hi; unpack2(acc[p], lo, hi);
        ho[(size_t)(r0 + 2 * p) * 128 + t] = lo;
        ho[(size_t)(r0 + 2 * p + 1) * 128 + t] = hi;
        hsT[t][2 * p] = lo; hsT[t][2 * p + 1] = hi;
    }
    __syncthreads();
#pragma unroll
    for (int p = 0; p < TM / 2; p++) acc[p] = 0ull;
    for (int k = 0; k < 128; k++) {
        float av = A[k * 128 + t];
        unsigned long long a2 = pack2(av, av);
#pragma unroll
        for (int p = 0; p < TM / 2; p++) fma2(acc[p], lds2(&hsT[k][2 * p]), a2);
    }
#pragma unroll
    for (int p = 0; p < TM / 2; p++) {
        float lo, hi; unpack2(acc[p], lo, hi);
        hAo[(size_t)(r0 + 2 * p) * 128 + t] = lo;
        hAo[(size_t)(r0 + 2 * p + 1) * 128 + t] = hi;
    }
}

// ---- E = mask([hA,h] @ [h,hA]^T) : symmetric GEMM, upper-tri tiles only -----
// 64x64 tiles, K=256. Off-diagonal tiles also write the smem-transposed mirror
// (E is symmetric pre-mask; adj is NOT symmetric, so mask per side).
// NOTE: As/Bs row stride MUST be a multiple of 4 floats (float4 smem reads).
constexpr int ET = 64;
__global__ void __launch_bounds__(256)
k_Egemm(const float* __restrict__ hA2, const float* __restrict__ h2,
        const float* __restrict__ adj2, float* __restrict__ E2,
        const float* __restrict__ hA1, const float* __restrict__ h1,
        const float* __restrict__ adj1, float* __restrict__ E1) {
    int blk = blockIdx.x;
    const float *hA, *hh, *adj; float* E; int N, b, tj, tk;
    if (blk < 288) {                 // 8 batches x 36 upper-tri tile pairs
        N = 512; b = blk / 36;
        int tp = blk % 36;
        tj = 0;
        while (tp >= 8 - tj) { tp -= 8 - tj; tj++; }
        tk = tj + tp;
        hA = hA2; hh = h2; adj = adj2; E = E2;
    } else {                          // 8 batches x 1 tile (N1=64)
        N = 64; b = blk - 288; tj = 0; tk = 0;
        hA = hA1; hh = h1; adj = adj1; E = E1;
    }
    int j0 = tj * ET, k0 = tk * ET;
    int t = threadIdx.x, tx = t & 15, ty = t >> 4;
    __shared__ float As[16][ET + 4];     // stride 68: float4-safe
    __shared__ float Bs[16][ET + 4];
    __shared__ float Es[ET][ET + 1];
    unsigned long long acc[2][4];
#pragma unroll
    for (int p = 0; p < 2; p++)
#pragma unroll
        for (int q = 0; q < 4; q++) acc[p][q] = 0ull;

    const float* A_hA = hA + ((size_t)b * N + j0) * 128;
    const float* A_h  = hh + ((size_t)b * N + j0) * 128;
    const float* B_h  = hh + ((size_t)b * N + k0) * 128;
    const float* B_hA = hA + ((size_t)b * N + k0) * 128;
    int lrow = t >> 2, ldq = t & 3;

    for (int dc = 0; dc < 256; dc += 16) {
        const float* sA = (dc < 128) ? (A_hA + dc) : (A_h + dc - 128);
        const float* sB = (dc < 128) ? (B_h + dc) : (B_hA + dc - 128);
        float4 va = *reinterpret_cast<const float4*>(&sA[(size_t)lrow * 128 + ldq * 4]);
        float4 vb = *reinterpret_cast<const float4*>(&sB[(size_t)lrow * 128 + ldq * 4]);
        __syncthreads();
        As[ldq * 4 + 0][lrow] = va.x; As[ldq * 4 + 1][lrow] = va.y;
        As[ldq * 4 + 2][lrow] = va.z; As[ldq * 4 + 3][lrow] = va.w;
        Bs[ldq * 4 + 0][lrow] = vb.x; Bs[ldq * 4 + 1][lrow] = vb.y;
        Bs[ldq * 4 + 2][lrow] = vb.z; Bs[ldq * 4 + 3][lrow] = vb.w;
        __syncthreads();
#pragma unroll
        for (int d = 0; d < 16; d++) {
            unsigned long long a2[2];
            a2[0] = lds2(&As[d][ty * 4]);
            a2[1] = lds2(&As[d][ty * 4 + 2]);
            float4 bv = *reinterpret_cast<const float4*>(&Bs[d][tx * 4]);
            unsigned long long b2[4] = {pack2(bv.x, bv.x), pack2(bv.y, bv.y),
                                        pack2(bv.z, bv.z), pack2(bv.w, bv.w)};
#pragma unroll
            for (int p = 0; p < 2; p++)
#pragma unroll
                for (int q = 0; q < 4; q++) fma2(acc[p][q], a2[p], b2[q]);
        }
    }
    __syncthreads();
#pragma unroll
    for (int p = 0; p < 2; p++)
#pragma unroll
        for (int q = 0; q < 4; q++) {
            float lo, hi; unpack2(acc[p][q], lo, hi);
            Es[ty * 4 + 2 * p][tx * 4 + q] = lo;
            Es[ty * 4 + 2 * p + 1][tx * 4 + q] = hi;
        }
    __syncthreads();
    size_t bNN = (size_t)b * N * N;
    for (int idx = t; idx < ET * ET; idx += 256) {
        int r = idx >> 6, c = idx & 63;
        size_t off = bNN + (size_t)(j0 + r) * N + k0 + c;
        float a = adj[off];
        E[off] = (a > 0.f) ? Es[r][c] : -1e30f;
    }
    if (tj != tk) {
        for (int idx = t; idx < ET * ET; idx += 256) {
            int r = idx >> 6, c = idx & 63;
            size_t off = bNN + (size_t)(k0 + r) * N + j0 + c;
            float a = adj[off];
            E[off] = (a > 0.f) ? Es[c][r] : -1e30f;
        }
    }
}

// ---------------- column softmax over axis-0, coalesced row-marching ---------
constexpr int CS = 32;
__global__ void __launch_bounds__(256)
k_colsoftmax(const float* __restrict__ E2, float* __restrict__ att2,
             const float* __restrict__ E1, float* __restrict__ att1) {
    int blk = blockIdx.x;
    const float* E; float* att; int N, b, k0;
    if (blk < 128) { N = 512; b = blk >> 4; k0 = (blk & 15) * CS; E = E2; att = att2; }
    else { int r = blk - 128; N = 64; b = r >> 1; k0 = (r & 1) * CS; E = E1; att = att1; }
    int t = threadIdx.x, c = t & 31, rg = t >> 5;       // 8 row-groups
    size_t base = (size_t)b * N * N + k0 + c;
    float m = -INFINITY, s = 0.f;
    for (int j = rg; j < N; j += 8) {
        float v = E[base + (size_t)j * N];
        float mn = fmaxf(m, v);
        s = s * expf(m - mn) + expf(v - mn);
        m = mn;
    }
    __shared__ float ms[8][33], ss[8][33];
    ms[rg][c] = m; ss[rg][c] = s;
    __syncthreads();
    if (rg == 0) {
        float M = ms[0][c];
#pragma unroll
        for (int r = 1; r < 8; r++) M = fmaxf(M, ms[r][c]);
        float S = 0.f;
#pragma unroll
        for (int r = 0; r < 8; r++) S += ss[r][c] * expf(ms[r][c] - M);
        ms[0][c] = M; ss[0][c] = 1.f / S;
    }
    __syncthreads();
    float M = ms[0][c], inv = ss[0][c];
    for (int j = rg; j < N; j += 8) {
        float v = E[base + (size_t)j * N];
        att[base + (size_t)j * N] = expf(v - M) * inv;
    }
}

// ---------------- hp = relu(att@h) ; gate  (merged, packed f32x2) ------------
constexpr int TMH = 16;
__global__ void __launch_bounds__(128)
k_hp_gate(const float* __restrict__ x2, const float* __restrict__ h2, const float* __restrict__ att2,
          const float* __restrict__ x1, const float* __restrict__ h1, const float* __restrict__ att1,
          const float* __restrict__ Wg, const float* __restrict__ bg,
          float* __restrict__ o2, float* __restrict__ o1) {
    __shared__ float attsT[512][TMH + 2];   // even row stride -> 8B-aligned lds2
    __shared__ float partial[TMH][4];
    __shared__ float coeff[TMH];
    int blk = blockIdx.x;
    const float *x, *hh, *att; float* out; int N, b, r0;
    if (blk < 256) { N = 512; b = blk >> 5; r0 = (blk & 31) * TMH; x = x2; hh = h2; att = att2; out = o2; }
    else { int r = blk - 256; N = 64; b = r >> 2; r0 = (r & 3) * TMH; x = x1; hh = h1; att = att1; out = o1; }
    int t = threadIdx.x, lane = t & 31, w = t >> 5;
    size_t bN = (size_t)b * N;
#pragma unroll
    for (int m = 0; m < TMH; m++)
        for (int j = t; j < N; j += 128) attsT[j][m] = att[(bN + r0 + m) * N + j];
    __syncthreads();
    unsigned long long acc[TMH / 2];
#pragma unroll
    for (int p = 0; p < TMH / 2; p++) acc[p] = 0ull;
    for (int j = 0; j < N; j++) {
        float hv = hh[(bN + j) * 128 + t];
        unsigned long long h2p = pack2(hv, hv);
#pragma unroll
        for (int p = 0; p < TMH / 2; p++) fma2(acc[p], lds2(&attsT[j][2 * p]), h2p);
    }
    float hp[TMH], xr[TMH];
#pragma unroll
    for (int p = 0; p < TMH / 2; p++) {
        float lo, hi; unpack2(acc[p], lo, hi);
        hp[2 * p] = fmaxf(lo, 0.f); hp[2 * p + 1] = fmaxf(hi, 0.f);
    }
    float wg0 = Wg[t], wg1 = Wg[128 + t];
#pragma unroll
    for (int m = 0; m < TMH; m++) {
        xr[m] = x[(bN + r0 + m) * 128 + t];
        float v = xr[m] * wg0 + hp[m] * wg1;
#pragma unroll
        for (int o = 16; o; o >>= 1) v += __shfl_down_sync(~0u, v, o);
        if (lane == 0) partial[m][w] = v;
    }
    __syncthreads();
    if (t < TMH)
        coeff[t] = sigmoidf(partial[t][0] + partial[t][1] + partial[t][2] + partial[t][3] + bg[0]);
    __syncthreads();
#pragma unroll
    for (int m = 0; m < TMH; m++) {
        float c = coeff[m];
        out[(bN + r0 + m) * 128 + t] = c * xr[m] + (1.f - c) * hp[m];
    }
}

// ---------------- U precompute (merged, packed f32x2, TM=32) -----------------
constexpr int TMU = 32;
__global__ void __launch_bounds__(128)
k_precU(const float* __restrict__ x1e, const float* __restrict__ x2e,
        const float* __restrict__ WA1, const float* __restrict__ bA1,
        const float* __restrict__ WB1, const float* __restrict__ bB1,
        float* __restrict__ U1A, float* __restrict__ U1B,
        float* __restrict__ U2A, float* __restrict__ U2B) {
    constexpr int T1 = (B * N1) / TMU;      // 16
    int i = blockIdx.x % 7;
    int tile = blockIdx.x / 7;
    const float* x; float *UA, *UB; int r0, dOff; float biasMul;
    if (tile < T1) { x = x1e; UA = U1A; UB = U1B; r0 = tile * TMU; dOff = 0; biasMul = 1.f; }
    else { x = x2e; UA = U2A; UB = U2B; r0 = (tile - T1) * TMU; dOff = 128; biasMul = 0.f; }
    int hh = threadIdx.x;
    __shared__ float xsT[128][TMU + 2];
#pragma unroll
    for (int m = 0; m < TMU; m++) xsT[hh][m] = x[(size_t)(r0 + m) * 128 + hh];
    __syncthreads();
    float ba = bA1[i * 128 + hh] * biasMul, bb = bB1[i * 128 + hh] * biasMul;
    unsigned long long accA[TMU / 2], accB[TMU / 2];
#pragma unroll
    for (int p = 0; p < TMU / 2; p++) { accA[p] = pack2(ba, ba); accB[p] = pack2(bb, bb); }
    const float* wa = WA1 + ((size_t)i * 256 + dOff) * 128;
    const float* wb = WB1 + ((size_t)i * 256 + dOff) * 128;
    for (int d = 0; d < 128; d++) {
        float wav = wa[(size_t)d * 128 + hh], wbv = wb[(size_t)d * 128 + hh];
        unsigned long long w2a = pack2(wav, wav), w2b = pack2(wbv, wbv);
#pragma unroll
        for (int p = 0; p < TMU / 2; p++) {
            unsigned long long xs2 = lds2(&xsT[d][2 * p]);
            fma2(accA[p], xs2, w2a);
            fma2(accB[p], xs2, w2b);
        }
    }
#pragma unroll
    for (int p = 0; p < TMU / 2; p++) {
        float lo, hi;
        unpack2(accA[p], lo, hi);
        UA[((size_t)(r0 + 2 * p) * NT + i) * 128 + hh] = lo;
        UA[((size_t)(r0 + 2 * p + 1) * NT + i) * 128 + hh] = hi;
        unpack2(accB[p], lo, hi);
        UB[((size_t)(r0 + 2 * p) * NT + i) * 128 + hh] = lo;
        UB[((size_t)(r0 + 2 * p + 1) * NT + i) * 128 + hh] = hi;
    }
}

// ---------------- intercept ---------------------------------------------------
__global__ void k_intercept(const float* __restrict__ h1e, const float* __restrict__ valid,
                            const float* __restrict__ Wi1, const float* __restrict__ bi1,
                            const float* __restrict__ Wi2, const float* __restrict__ bi2,
                            float* __restrict__ out) {
    int b = blockIdx.x, t = threadIdx.x;
    int lane = t & 31, w = t >> 5;
    __shared__ float pooled[128];
    __shared__ float red[4];
    float p = 0.f;
    for (int j = 0; j < N1; j++)
        p = fmaf(h1e[((size_t)b * N1 + j) * 128 + t], valid[b * N1 + j], p);
    pooled[t] = p;
    __syncthreads();
    float acc = bi1[t];
    for (int d = 0; d < 128; d++) acc = fmaf(pooled[d], Wi1[d * 128 + t], acc);
    float v = fmaxf(acc, 0.f) * Wi2[t];
#pragma unroll
    for (int o = 16; o; o >>= 1) v += __shfl_down_sync(~0u, v, o);
    if (lane == 0) red[w] = v;
    __syncthreads();
    if (t == 0) {
        float s = red[0] + red[1] + red[2] + red[3] + bi2[0];
        s = 4.f * sigmoidf(s);
        float val = s / 7.f;
        for (int i = 0; i < NT; i++) out[b * NT + i] = val;
    }
}

// ---------------- sparse energies (dm computed inline from dmv) ---------------
__global__ void k_energy(const float* __restrict__ U1A, const float* __restrict__ U1B,
                         const float* __restrict__ U2A, const float* __restrict__ U2B,
                         const float* __restrict__ WA2, const float* __restrict__ bA2,
                         const float* __restrict__ WB2, const float* __restrict__ bB2,
                         const float* __restrict__ Cc, const float* __restrict__ A_int,
                         const float* __restrict__ dmv, float* __restrict__ epart) {
    int j = blockIdx.x % N1;
    int bi = blockIdx.x / N1;
    int i = bi % NT;
    int b = bi / NT;
    int t = threadIdx.x, lane = t & 31, w = t >> 5;
    __shared__ float u1a[128], u1b[128], wa2[128], wb2[128];
    __shared__ float part[4];
    u1a[t] = U1A[(((size_t)b * N1 + j) * NT + i) * 128 + t];
    u1b[t] = U1B[(((size_t)b * N1 + j) * NT + i) * 128 + t];
    wa2[t] = WA2[i * 128 + t];
    wb2[t] = WB2[i * 128 + t];
    __syncthreads();
    float bc = c_bconstraint[i];
    float bcinv = 1.f / (3.f * bc * bc);
    float Ci = Cc[i], ba2 = bA2[i], bb2 = bB2[i];
    const float* aint_row = A_int + (((size_t)b * NT + i) * N1 + j) * N2;
    const float* dmv_row = dmv + ((size_t)b * N1 + j) * N2 * 3;
    float esum = 0.f;
    for (int k = w; k < N2; k += 4) {
        float av = aint_row[k];
        if (av != 0.f) {
            const float* u2a = U2A + (((size_t)b * N2 + k) * NT + i) * 128;
            const float* u2b = U2B + (((size_t)b * N2 + k) * NT + i) * 128;
            float sA = 0.f, sB = 0.f;
#pragma unroll
            for (int q = 0; q < 4; q++) {
                int d = lane + 32 * q;
                sA = fmaf(fmaxf(u1a[d] + u2a[d], 0.f), wa2[d], sA);
                sB = fmaf(fmaxf(u1b[d] + u2b[d], 0.f), wb2[d], sB);
            }
#pragma unroll
            for (int o = 16; o; o >>= 1) {
                sA += __shfl_xor_sync(~0u, sA, o);
                sB += __shfl_xor_sync(~0u, sB, o);
            }
            if (lane == 0) {
                float xx = dmv_row[3 * k + 0];
                float yy = dmv_row[3 * k + 1];
                float zz = dmv_row[3 * k + 2];
                float dmval = sqrtf(xx * xx + yy * yy + zz * zz + 1e-10f);
                dmval = (dmval < 0.5f) ? 1e10f : dmval;
                float Aa = 4.f * sigmoidf(sA + ba2);
                float Bp = sigmoidf(sB + bb2) * (2.f * bcinv) + bcinv;
                float dd = dmval - Ci;
                esum += Aa * (Bp * dd * dd - 1.f) * av;
            }
        }
    }
    if (lane == 0) part[w] = esum;
    __syncthreads();
    if (t == 0) epart[blockIdx.x] = part[0] + part[1] + part[2] + part[3];
}

// ---------------- deterministic reduce ----------------------------------------
__global__ void k_reduce(const float* __restrict__ epart, float* __restrict__ out) {
    int t = threadIdx.x;
    if (t < B * NT) {
        float s = 0.f;
        for (int j = 0; j < N1; j++) s += epart[(size_t)t * N1 + j];
        out[t] += s;
    }
}

// ---------------- orchestration ------------------------------------------------
extern "C" void kernel_launch(void* const* d_in, const int* in_sizes, int n_in,
                              void* d_out, int out_size) {
    const float* h1     = (const float*)d_in[0];
    const float* adj1   = (const float*)d_in[1];
    const float* h2     = (const float*)d_in[2];
    const float* adj2   = (const float*)d_in[3];
    const float* A_int  = (const float*)d_in[4];
    const float* dmv    = (const float*)d_in[5];
    const float* valid  = (const float*)d_in[6];
    const float* W_embed= (const float*)d_in[7];
    const float* gW     = (const float*)d_in[8];
    const float* gWb    = (const float*)d_in[9];
    const float* gA     = (const float*)d_in[10];
    const float* gGateW = (const float*)d_in[11];
    const float* gGateb = (const float*)d_in[12];
    const float* WA1    = (const float*)d_in[13];
    const float* bA1    = (const float*)d_in[14];
    const float* WA2    = (const float*)d_in[15];
    const float* bA2    = (const float*)d_in[16];
    const float* WB1    = (const float*)d_in[17];
    const float* bB1    = (const float*)d_in[18];
    const float* WB2    = (const float*)d_in[19];
    const float* bB2    = (const float*)d_in[20];
    const float* Cc     = (const float*)d_in[21];
    const float* Wi1    = (const float*)d_in[22];
    const float* bi1    = (const float*)d_in[23];
    const float* Wi2    = (const float*)d_in[24];
    const float* bi2    = (const float*)d_in[25];
    float* out = (float*)d_out;

    float* S = nullptr;
    cudaGetSymbolAddress((void**)&S, g_scratch);

    float* h1buf[2] = {S + OFF_H1A, S + OFF_H1B};
    float* h2buf[2] = {S + OFF_H2A, S + OFF_H2B};
    float* t1   = S + OFF_T1;
    float* ta1  = S + OFF_TA1;
    float* t2   = S + OFF_T2;
    float* ta2  = S + OFF_TA2;
    float* att1 = S + OFF_ATT1;
    float* att2 = S + OFF_ATT2;
    float* E1   = S + OFF_E1;
    float* E2   = S + OFF_E2;
    float* U1A  = S + OFF_U1A;
    float* U1B  = S + OFF_U1B;
    float* U2A  = S + OFF_U2A;
    float* U2B  = S + OFF_U2B;
    float* ep   = S + OFF_EP;

    // 1. embed (merged)
    k_embed<8><<<(B * N1 + B * N2) / 8, 128>>>(h1, h2, W_embed, h1buf[0], h2buf[0]);

    // 2. GAT layers (graph1 + graph2 merged per stage)
    int cur = 0;
    for (int l = 0; l < NL; l++) {
        const float* W  = gW + (size_t)l * D * D;
        const float* Wb = gWb + (size_t)l * D;
        const float* A  = gA + (size_t)l * D * D;
        const float* Gw = gGateW + (size_t)l * 2 * D;
        const float* Gb = gGateb + l;
        int nxt = cur ^ 1;
        k_h_hA<8><<<(B * N1 + B * N2) / 8, 128>>>(h1buf[cur], h2buf[cur], W, Wb, A,
                                                  t1, ta1, t2, ta2);
        k_Egemm<<<288 + 8, 256>>>(ta2, t2, adj2, E2, ta1, t1, adj1, E1);
        k_colsoftmax<<<128 + 16, 256>>>(E2, att2, E1, att1);
        k_hp_gate<<<256 + 32, 128>>>(h2buf[cur], t2, att2, h1buf[cur], t1, att1,
                                     Gw, Gb, h2buf[nxt], h1buf[nxt]);
        cur = nxt;
    }
    const float* h1e = h1buf[cur];
    const float* h2e = h2buf[cur];

    // 3. factored MLP first layer (merged)
    k_precU<<<7 * ((B * N1 + B * N2) / TMU), 128>>>(h1e, h2e, WA1, bA1, WB1, bB1,
                                                    U1A, U1B, U2A, U2B);

    // 4. intercept (initializes out), sparse energies (dm inline), reduce
    k_intercept<<<B, 128>>>(h1e, valid, Wi1, bi1, Wi2, bi2, out);
    k_energy<<<B * NT * N1, 128>>>(U1A, U1B, U2A, U2B, WA2, bA2, WB2, bB2,
                                   Cc, A_int, dmv, ep);
    k_reduce<<<1, 64>>>(ep, out);
}

// round 11
// speedup vs baseline: 2.6036x; 1.0757x over previous
#include <cuda_runtime.h>
#include <math.h>

constexpr int B = 8, N1 = 64, N2 = 512, D = 128, NL = 3, H = 128, NT = 7;

// ---------------- scratch (static device memory) ----------------------------
constexpr size_t SZ_H1   = (size_t)B * N1 * D;
constexpr size_t SZ_H2   = (size_t)B * N2 * D;
constexpr size_t SZ_ATT1 = (size_t)B * N1 * N1;
constexpr size_t SZ_ATT2 = (size_t)B * N2 * N2;
constexpr size_t SZ_U1   = (size_t)B * N1 * NT * H;
constexpr size_t SZ_U2   = (size_t)B * N2 * NT * H;
constexpr size_t SZ_EP   = (size_t)B * NT * N1;
constexpr size_t SZ_ST1  = (size_t)B * N1;    // per-column stats
constexpr size_t SZ_ST2  = (size_t)B * N2;

constexpr size_t OFF_H1A  = 0;
constexpr size_t OFF_H1B  = OFF_H1A  + SZ_H1;
constexpr size_t OFF_H2A  = OFF_H1B  + SZ_H1;
constexpr size_t OFF_H2B  = OFF_H2A  + SZ_H2;
constexpr size_t OFF_T1   = OFF_H2B  + SZ_H2;
constexpr size_t OFF_TA1  = OFF_T1   + SZ_H1;
constexpr size_t OFF_T2   = OFF_TA1  + SZ_H1;
constexpr size_t OFF_TA2  = OFF_T2   + SZ_H2;
constexpr size_t OFF_E1   = OFF_TA2  + SZ_H2;
constexpr size_t OFF_E2   = OFF_E1   + SZ_ATT1;
constexpr size_t OFF_M1   = OFF_E2   + SZ_ATT2;
constexpr size_t OFF_S1   = OFF_M1   + SZ_ST1;
constexpr size_t OFF_M2   = OFF_S1   + SZ_ST1;
constexpr size_t OFF_S2   = OFF_M2   + SZ_ST2;
constexpr size_t OFF_U1A  = OFF_S2   + SZ_ST2;
constexpr size_t OFF_U1B  = OFF_U1A  + SZ_U1;
constexpr size_t OFF_U2A  = OFF_U1B  + SZ_U1;
constexpr size_t OFF_U2B  = OFF_U2A  + SZ_U2;
constexpr size_t OFF_EP   = OFF_U2B  + SZ_U2;
constexpr size_t SCRATCH_TOTAL = OFF_EP + SZ_EP;

__device__ float g_scratch[SCRATCH_TOTAL];

__constant__ float c_bconstraint[NT] = {1.159f, 0.448f, 0.927f, 0.902f, 0.349f, 0.789f, 0.198f};

__device__ __forceinline__ float sigmoidf(float x) { return 1.f / (1.f + expf(-x)); }

// ---------------- packed fp32x2 helpers (sm_103a dual-fp32 pipe) ------------
__device__ __forceinline__ unsigned long long pack2(float lo, float hi) {
    unsigned long long r;
    asm("mov.b64 %0, {%1,%2};" : "=l"(r) : "f"(lo), "f"(hi));
    return r;
}
__device__ __forceinline__ void unpack2(unsigned long long v, float& lo, float& hi) {
    asm("mov.b64 {%0,%1}, %2;" : "=f"(lo), "=f"(hi) : "l"(v));
}
__device__ __forceinline__ void fma2(unsigned long long& d, unsigned long long a,
                                     unsigned long long b) {
    asm("fma.rn.f32x2 %0, %1, %2, %0;" : "+l"(d) : "l"(a), "l"(b));
}
__device__ __forceinline__ unsigned long long lds2(const float* p) {
    return *reinterpret_cast<const unsigned long long*>(p);
}

// ---------------- embedding (both graphs, one launch) ------------------------
template <int TM>
__global__ void k_embed(const float* __restrict__ x1, const float* __restrict__ x2,
                        const float* __restrict__ W,
                        float* __restrict__ o1, float* __restrict__ o2) {
    constexpr int T1 = (B * N1) / TM;
    int blk = blockIdx.x;
    const float* x; float* out; int r0;
    if (blk < T1) { x = x1; out = o1; r0 = blk * TM; }
    else          { x = x2; out = o2; r0 = (blk - T1) * TM; }
    int t = threadIdx.x;
    __shared__ float xs[TM][56];
    for (int idx = t; idx < TM * 56; idx += 128) {
        int m = idx / 56, d = idx % 56;
        xs[m][d] = x[(size_t)(r0 + m) * 56 + d];
    }
    __syncthreads();
    float acc[TM];
#pragma unroll
    for (int m = 0; m < TM; m++) acc[m] = 0.f;
    for (int k = 0; k < 56; k++) {
        float wv = W[k * 128 + t];
#pragma unroll
        for (int m = 0; m < TM; m++) acc[m] = fmaf(xs[m][k], wv, acc[m]);
    }
#pragma unroll
    for (int m = 0; m < TM; m++) out[(size_t)(r0 + m) * 128 + t] = acc[m];
}

// ---------------- h = x@W + Wb ; hA = h@A  (merged, packed f32x2) ------------
template <int TM>   // TM must be even
__global__ void __launch_bounds__(128)
k_h_hA(const float* __restrict__ x1, const float* __restrict__ x2,
       const float* __restrict__ W, const float* __restrict__ Wb,
       const float* __restrict__ A,
       float* __restrict__ h1o, float* __restrict__ hA1o,
       float* __restrict__ h2o, float* __restrict__ hA2o) {
    constexpr int T1 = (B * N1) / TM;
    int blk = blockIdx.x;
    const float* x; float *ho, *hAo; int r0;
    if (blk < T1) { x = x1; ho = h1o; hAo = hA1o; r0 = blk * TM; }
    else          { x = x2; ho = h2o; hAo = hA2o; r0 = (blk - T1) * TM; }
    int t = threadIdx.x;
    __shared__ float xsT[128][TM + 2];
    __shared__ float hsT[128][TM + 2];
#pragma unroll
    for (int m = 0; m < TM; m++) xsT[t][m] = x[(size_t)(r0 + m) * 128 + t];
    __syncthreads();
    unsigned long long acc[TM / 2];
    float wb = Wb[t];
#pragma unroll
    for (int p = 0; p < TM / 2; p++) acc[p] = pack2(wb, wb);
    for (int k = 0; k < 128; k++) {
        float wv = W[k * 128 + t];
        unsigned long long w2 = pack2(wv, wv);
#pragma unroll
        for (int p = 0; p < TM / 2; p++) fma2(acc[p], lds2(&xsT[k][2 * p]), w2);
    }
#pragma unroll
    for (int p = 0; p < TM / 2; p++) {
        float lo, hi; unpack2(acc[p], lo, hi);
        ho[(size_t)(r0 + 2 * p) * 128 + t] = lo;
        ho[(size_t)(r0 + 2 * p + 1) * 128 + t] = hi;
        hsT[t][2 * p] = lo; hsT[t][2 * p + 1] = hi;
    }
    __syncthreads();
#pragma unroll
    for (int p = 0; p < TM / 2; p++) acc[p] = 0ull;
    for (int k = 0; k < 128; k++) {
        float av = A[k * 128 + t];
        unsigned long long a2 = pack2(av, av);
#pragma unroll
        for (int p = 0; p < TM / 2; p++) fma2(acc[p], lds2(&hsT[k][2 * p]), a2);
    }
#pragma unroll
    for (int p = 0; p < TM / 2; p++) {
        float lo, hi; unpack2(acc[p], lo, hi);
        hAo[(size_t)(r0 + 2 * p) * 128 + t] = lo;
        hAo[(size_t)(r0 + 2 * p + 1) * 128 + t] = hi;
    }
}

// ---- E = mask([hA,h] @ [h,hA]^T) : symmetric GEMM, upper-tri tiles only -----
constexpr int ET = 64;
__global__ void __launch_bounds__(256)
k_Egemm(const float* __restrict__ hA2, const float* __restrict__ h2,
        const float* __restrict__ adj2, float* __restrict__ E2,
        const float* __restrict__ hA1, const float* __restrict__ h1,
        const float* __restrict__ adj1, float* __restrict__ E1) {
    int blk = blockIdx.x;
    const float *hA, *hh, *adj; float* E; int N, b, tj, tk;
    if (blk < 288) {                 // 8 batches x 36 upper-tri tile pairs
        N = 512; b = blk / 36;
        int tp = blk % 36;
        tj = 0;
        while (tp >= 8 - tj) { tp -= 8 - tj; tj++; }
        tk = tj + tp;
        hA = hA2; hh = h2; adj = adj2; E = E2;
    } else {                          // 8 batches x 1 tile (N1=64)
        N = 64; b = blk - 288; tj = 0; tk = 0;
        hA = hA1; hh = h1; adj = adj1; E = E1;
    }
    int j0 = tj * ET, k0 = tk * ET;
    int t = threadIdx.x, tx = t & 15, ty = t >> 4;
    __shared__ float As[16][ET + 4];     // stride 68: float4-safe
    __shared__ float Bs[16][ET + 4];
    __shared__ float Es[ET][ET + 1];
    unsigned long long acc[2][4];
#pragma unroll
    for (int p = 0; p < 2; p++)
#pragma unroll
        for (int q = 0; q < 4; q++) acc[p][q] = 0ull;

    const float* A_hA = hA + ((size_t)b * N + j0) * 128;
    const float* A_h  = hh + ((size_t)b * N + j0) * 128;
    const float* B_h  = hh + ((size_t)b * N + k0) * 128;
    const float* B_hA = hA + ((size_t)b * N + k0) * 128;
    int lrow = t >> 2, ldq = t & 3;

    for (int dc = 0; dc < 256; dc += 16) {
        const float* sA = (dc < 128) ? (A_hA + dc) : (A_h + dc - 128);
        const float* sB = (dc < 128) ? (B_h + dc) : (B_hA + dc - 128);
        float4 va = *reinterpret_cast<const float4*>(&sA[(size_t)lrow * 128 + ldq * 4]);
        float4 vb = *reinterpret_cast<const float4*>(&sB[(size_t)lrow * 128 + ldq * 4]);
        __syncthreads();
        As[ldq * 4 + 0][lrow] = va.x; As[ldq * 4 + 1][lrow] = va.y;
        As[ldq * 4 + 2][lrow] = va.z; As[ldq * 4 + 3][lrow] = va.w;
        Bs[ldq * 4 + 0][lrow] = vb.x; Bs[ldq * 4 + 1][lrow] = vb.y;
        Bs[ldq * 4 + 2][lrow] = vb.z; Bs[ldq * 4 + 3][lrow] = vb.w;
        __syncthreads();
#pragma unroll
        for (int d = 0; d < 16; d++) {
            unsigned long long a2[2];
            a2[0] = lds2(&As[d][ty * 4]);
            a2[1] = lds2(&As[d][ty * 4 + 2]);
            float4 bv = *reinterpret_cast<const float4*>(&Bs[d][tx * 4]);
            unsigned long long b2[4] = {pack2(bv.x, bv.x), pack2(bv.y, bv.y),
                                        pack2(bv.z, bv.z), pack2(bv.w, bv.w)};
#pragma unroll
            for (int p = 0; p < 2; p++)
#pragma unroll
                for (int q = 0; q < 4; q++) fma2(acc[p][q], a2[p], b2[q]);
        }
    }
    __syncthreads();
#pragma unroll
    for (int p = 0; p < 2; p++)
#pragma unroll
        for (int q = 0; q < 4; q++) {
            float lo, hi; unpack2(acc[p][q], lo, hi);
            Es[ty * 4 + 2 * p][tx * 4 + q] = lo;
            Es[ty * 4 + 2 * p + 1][tx * 4 + q] = hi;
        }
    __syncthreads();
    size_t bNN = (size_t)b * N * N;
    for (int idx = t; idx < ET * ET; idx += 256) {
        int r = idx >> 6, c = idx & 63;
        size_t off = bNN + (size_t)(j0 + r) * N + k0 + c;
        float a = adj[off];
        E[off] = (a > 0.f) ? Es[r][c] : -1e30f;
    }
    if (tj != tk) {
        for (int idx = t; idx < ET * ET; idx += 256) {
            int r = idx >> 6, c = idx & 63;
            size_t off = bNN + (size_t)(k0 + r) * N + j0 + c;
            float a = adj[off];
            E[off] = (a > 0.f) ? Es[c][r] : -1e30f;
        }
    }
}

// ---- per-column softmax stats: M_k = max_j E[j,k], invS_k = 1/sum exp ------
// single online pass, 512 threads (16 row-groups), coalesced row-marching.
constexpr int CS = 32;
__global__ void __launch_bounds__(512)
k_colstats(const float* __restrict__ E2, float* __restrict__ M2, float* __restrict__ S2,
           const float* __restrict__ E1, float* __restrict__ M1, float* __restrict__ S1) {
    int blk = blockIdx.x;
    const float* E; float *Mo, *So; int N, b, k0;
    if (blk < 128) { N = 512; b = blk >> 4; k0 = (blk & 15) * CS; E = E2; Mo = M2; So = S2; }
    else { int r = blk - 128; N = 64; b = r >> 1; k0 = (r & 1) * CS; E = E1; Mo = M1; So = S1; }
    int t = threadIdx.x, c = t & 31, rg = t >> 5;      // 16 row-groups
    size_t base = (size_t)b * N * N + k0 + c;
    float m = -INFINITY, s = 0.f;
    for (int j = rg; j < N; j += 16) {
        float v = E[base + (size_t)j * N];
        float mn = fmaxf(m, v);
        s = s * expf(m - mn) + expf(v - mn);
        m = mn;
    }
    __shared__ float ms[16][33], ss[16][33];
    ms[rg][c] = m; ss[rg][c] = s;
    __syncthreads();
    if (rg == 0) {
        float M = ms[0][c];
#pragma unroll
        for (int r = 1; r < 16; r++) M = fmaxf(M, ms[r][c]);
        float S = 0.f;
#pragma unroll
        for (int r = 0; r < 16; r++) S += ss[r][c] * expf(ms[r][c] - M);
        Mo[(size_t)b * N + k0 + c] = M;
        So[(size_t)b * N + k0 + c] = 1.f / S;
    }
}

// ---- hp = relu(att@h) ; gate ; att computed on the fly from E + stats -------
constexpr int TMH = 16;
__global__ void __launch_bounds__(128)
k_hp_gate(const float* __restrict__ x2, const float* __restrict__ h2,
          const float* __restrict__ E2, const float* __restrict__ M2, const float* __restrict__ S2,
          const float* __restrict__ x1, const float* __restrict__ h1,
          const float* __restrict__ E1, const float* __restrict__ M1, const float* __restrict__ S1,
          const float* __restrict__ Wg, const float* __restrict__ bg,
          float* __restrict__ o2, float* __restrict__ o1) {
    __shared__ float attsT[512][TMH + 2];   // even row stride -> 8B-aligned lds2
    __shared__ float partial[TMH][4];
    __shared__ float coeff[TMH];
    int blk = blockIdx.x;
    const float *x, *hh, *E, *Mst, *Sst; float* out; int N, b, r0;
    if (blk < 256) { N = 512; b = blk >> 5; r0 = (blk & 31) * TMH;
                     x = x2; hh = h2; E = E2; Mst = M2; Sst = S2; out = o2; }
    else { int r = blk - 256; N = 64; b = r >> 2; r0 = (r & 3) * TMH;
           x = x1; hh = h1; E = E1; Mst = M1; Sst = S1; out = o1; }
    int t = threadIdx.x, lane = t & 31, w = t >> 5;
    size_t bN = (size_t)b * N;
    // stage att rows: att[i,j] = exp(E[i,j]-M_j)*invS_j  (masked E=-1e30 -> 0)
    for (int j = t; j < N; j += 128) {
        float Mj = Mst[bN + j], Sj = Sst[bN + j];
#pragma unroll
        for (int m = 0; m < TMH; m++)
            attsT[j][m] = expf(E[(bN + r0 + m) * N + j] - Mj) * Sj;
    }
    __syncthreads();
    unsigned long long acc[TMH / 2];
#pragma unroll
    for (int p = 0; p < TMH / 2; p++) acc[p] = 0ull;
    for (int j = 0; j < N; j++) {
        float hv = hh[(bN + j) * 128 + t];
        unsigned long long h2p = pack2(hv, hv);
#pragma unroll
        for (int p = 0; p < TMH / 2; p++) fma2(acc[p], lds2(&attsT[j][2 * p]), h2p);
    }
    float hp[TMH], xr[TMH];
#pragma unroll
    for (int p = 0; p < TMH / 2; p++) {
        float lo, hi; unpack2(acc[p], lo, hi);
        hp[2 * p] = fmaxf(lo, 0.f); hp[2 * p + 1] = fmaxf(hi, 0.f);
    }
    float wg0 = Wg[t], wg1 = Wg[128 + t];
#pragma unroll
    for (int m = 0; m < TMH; m++) {
        xr[m] = x[(bN + r0 + m) * 128 + t];
        float v = xr[m] * wg0 + hp[m] * wg1;
#pragma unroll
        for (int o = 16; o; o >>= 1) v += __shfl_down_sync(~0u, v, o);
        if (lane == 0) partial[m][w] = v;
    }
    __syncthreads();
    if (t < TMH)
        coeff[t] = sigmoidf(partial[t][0] + partial[t][1] + partial[t][2] + partial[t][3] + bg[0]);
    __syncthreads();
#pragma unroll
    for (int m = 0; m < TMH; m++) {
        float c = coeff[m];
        out[(bN + r0 + m) * 128 + t] = c * xr[m] + (1.f - c) * hp[m];
    }
}

// ---------------- U precompute (merged, packed f32x2, TM=32) -----------------
constexpr int TMU = 32;
__global__ void __launch_bounds__(128)
k_precU(const float* __restrict__ x1e, const float* __restrict__ x2e,
        const float* __restrict__ WA1, const float* __restrict__ bA1,
        const float* __restrict__ WB1, const float* __restrict__ bB1,
        float* __restrict__ U1A, float* __restrict__ U1B,
        float* __restrict__ U2A, float* __restrict__ U2B) {
    constexpr int T1 = (B * N1) / TMU;      // 16
    int i = blockIdx.x % 7;
    int tile = blockIdx.x / 7;
    const float* x; float *UA, *UB; int r0, dOff; float biasMul;
    if (tile < T1) { x = x1e; UA = U1A; UB = U1B; r0 = tile * TMU; dOff = 0; biasMul = 1.f; }
    else { x = x2e; UA = U2A; UB = U2B; r0 = (tile - T1) * TMU; dOff = 128; biasMul = 0.f; }
    int hh = threadIdx.x;
    __shared__ float xsT[128][TMU + 2];
#pragma unroll
    for (int m = 0; m < TMU; m++) xsT[hh][m] = x[(size_t)(r0 + m) * 128 + hh];
    __syncthreads();
    float ba = bA1[i * 128 + hh] * biasMul, bb = bB1[i * 128 + hh] * biasMul;
    unsigned long long accA[TMU / 2], accB[TMU / 2];
#pragma unroll
    for (int p = 0; p < TMU / 2; p++) { accA[p] = pack2(ba, ba); accB[p] = pack2(bb, bb); }
    const float* wa = WA1 + ((size_t)i * 256 + dOff) * 128;
    const float* wb = WB1 + ((size_t)i * 256 + dOff) * 128;
    for (int d = 0; d < 128; d++) {
        float wav = wa[(size_t)d * 128 + hh], wbv = wb[(size_t)d * 128 + hh];
        unsigned long long w2a = pack2(wav, wav), w2b = pack2(wbv, wbv);
#pragma unroll
        for (int p = 0; p < TMU / 2; p++) {
            unsigned long long xs2 = lds2(&xsT[d][2 * p]);
            fma2(accA[p], xs2, w2a);
            fma2(accB[p], xs2, w2b);
        }
    }
#pragma unroll
    for (int p = 0; p < TMU / 2; p++) {
        float lo, hi;
        unpack2(accA[p], lo, hi);
        UA[((size_t)(r0 + 2 * p) * NT + i) * 128 + hh] = lo;
        UA[((size_t)(r0 + 2 * p + 1) * NT + i) * 128 + hh] = hi;
        unpack2(accB[p], lo, hi);
        UB[((size_t)(r0 + 2 * p) * NT + i) * 128 + hh] = lo;
        UB[((size_t)(r0 + 2 * p + 1) * NT + i) * 128 + hh] = hi;
    }
}

// ---------------- intercept ---------------------------------------------------
__global__ void k_intercept(const float* __restrict__ h1e, const float* __restrict__ valid,
                            const float* __restrict__ Wi1, const float* __restrict__ bi1,
                            const float* __restrict__ Wi2, const float* __restrict__ bi2,
                            float* __restrict__ out) {
    int b = blockIdx.x, t = threadIdx.x;
    int lane = t & 31, w = t >> 5;
    __shared__ float pooled[128];
    __shared__ float red[4];
    float p = 0.f;
    for (int j = 0; j < N1; j++)
        p = fmaf(h1e[((size_t)b * N1 + j) * 128 + t], valid[b * N1 + j], p);
    pooled[t] = p;
    __syncthreads();
    float acc = bi1[t];
    for (int d = 0; d < 128; d++) acc = fmaf(pooled[d], Wi1[d * 128 + t], acc);
    float v = fmaxf(acc, 0.f) * Wi2[t];
#pragma unroll
    for (int o = 16; o; o >>= 1) v += __shfl_down_sync(~0u, v, o);
    if (lane == 0) red[w] = v;
    __syncthreads();
    if (t == 0) {
        float s = red[0] + red[1] + red[2] + red[3] + bi2[0];
        s = 4.f * sigmoidf(s);
        float val = s / 7.f;
        for (int i = 0; i < NT; i++) out[b * NT + i] = val;
    }
}

// ---------------- sparse energies (dm computed inline from dmv) ---------------
__global__ void k_energy(const float* __restrict__ U1A, const float* __restrict__ U1B,
                         const float* __restrict__ U2A, const float* __restrict__ U2B,
                         const float* __restrict__ WA2, const float* __restrict__ bA2,
                         const float* __restrict__ WB2, const float* __restrict__ bB2,
                         const float* __restrict__ Cc, const float* __restrict__ A_int,
                         const float* __restrict__ dmv, float* __restrict__ epart) {
    int j = blockIdx.x % N1;
    int bi = blockIdx.x / N1;
    int i = bi % NT;
    int b = bi / NT;
    int t = threadIdx.x, lane = t & 31, w = t >> 5;
    __shared__ float u1a[128], u1b[128], wa2[128], wb2[128];
    __shared__ float part[4];
    u1a[t] = U1A[(((size_t)b * N1 + j) * NT + i) * 128 + t];
    u1b[t] = U1B[(((size_t)b * N1 + j) * NT + i) * 128 + t];
    wa2[t] = WA2[i * 128 + t];
    wb2[t] = WB2[i * 128 + t];
    __syncthreads();
    float bc = c_bconstraint[i];
    float bcinv = 1.f / (3.f * bc * bc);
    float Ci = Cc[i], ba2 = bA2[i], bb2 = bB2[i];
    const float* aint_row = A_int + (((size_t)b * NT + i) * N1 + j) * N2;
    const float* dmv_row = dmv + ((size_t)b * N1 + j) * N2 * 3;
    float esum = 0.f;
    for (int k = w; k < N2; k += 4) {
        float av = aint_row[k];
        if (av != 0.f) {
            const float* u2a = U2A + (((size_t)b * N2 + k) * NT + i) * 128;
            const float* u2b = U2B + (((size_t)b * N2 + k) * NT + i) * 128;
            float sA = 0.f, sB = 0.f;
#pragma unroll
            for (int q = 0; q < 4; q++) {
                int d = lane + 32 * q;
                sA = fmaf(fmaxf(u1a[d] + u2a[d], 0.f), wa2[d], sA);
                sB = fmaf(fmaxf(u1b[d] + u2b[d], 0.f), wb2[d], sB);
            }
#pragma unroll
            for (int o = 16; o; o >>= 1) {
                sA += __shfl_xor_sync(~0u, sA, o);
                sB += __shfl_xor_sync(~0u, sB, o);
            }
            if (lane == 0) {
                float xx = dmv_row[3 * k + 0];
                float yy = dmv_row[3 * k + 1];
                float zz = dmv_row[3 * k + 2];
                float dmval = sqrtf(xx * xx + yy * yy + zz * zz + 1e-10f);
                dmval = (dmval < 0.5f) ? 1e10f : dmval;
                float Aa = 4.f * sigmoidf(sA + ba2);
                float Bp = sigmoidf(sB + bb2) * (2.f * bcinv) + bcinv;
                float dd = dmval - Ci;
                esum += Aa * (Bp * dd * dd - 1.f) * av;
            }
        }
    }
    if (lane == 0) part[w] = esum;
    __syncthreads();
    if (t == 0) epart[blockIdx.x] = part[0] + part[1] + part[2] + part[3];
}

// ---------------- deterministic reduce ----------------------------------------
__global__ void k_reduce(const float* __restrict__ epart, float* __restrict__ out) {
    int t = threadIdx.x;
    if (t < B * NT) {
        float s = 0.f;
        for (int j = 0; j < N1; j++) s += epart[(size_t)t * N1 + j];
        out[t] += s;
    }
}

// ---------------- orchestration ------------------------------------------------
extern "C" void kernel_launch(void* const* d_in, const int* in_sizes, int n_in,
                              void* d_out, int out_size) {
    const float* h1     = (const float*)d_in[0];
    const float* adj1   = (const float*)d_in[1];
    const float* h2     = (const float*)d_in[2];
    const float* adj2   = (const float*)d_in[3];
    const float* A_int  = (const float*)d_in[4];
    const float* dmv    = (const float*)d_in[5];
    const float* valid  = (const float*)d_in[6];
    const float* W_embed= (const float*)d_in[7];
    const float* gW     = (const float*)d_in[8];
    const float* gWb    = (const float*)d_in[9];
    const float* gA     = (const float*)d_in[10];
    const float* gGateW = (const float*)d_in[11];
    const float* gGateb = (const float*)d_in[12];
    const float* WA1    = (const float*)d_in[13];
    const float* bA1    = (const float*)d_in[14];
    const float* WA2    = (const float*)d_in[15];
    const float* bA2    = (const float*)d_in[16];
    const float* WB1    = (const float*)d_in[17];
    const float* bB1    = (const float*)d_in[18];
    const float* WB2    = (const float*)d_in[19];
    const float* bB2    = (const float*)d_in[20];
    const float* Cc     = (const float*)d_in[21];
    const float* Wi1    = (const float*)d_in[22];
    const float* bi1    = (const float*)d_in[23];
    const float* Wi2    = (const float*)d_in[24];
    const float* bi2    = (const float*)d_in[25];
    float* out = (float*)d_out;

    float* S = nullptr;
    cudaGetSymbolAddress((void**)&S, g_scratch);

    float* h1buf[2] = {S + OFF_H1A, S + OFF_H1B};
    float* h2buf[2] = {S + OFF_H2A, S + OFF_H2B};
    float* t1   = S + OFF_T1;
    float* ta1  = S + OFF_TA1;
    float* t2   = S + OFF_T2;
    float* ta2  = S + OFF_TA2;
    float* E1   = S + OFF_E1;
    float* E2   = S + OFF_E2;
    float* M1   = S + OFF_M1;
    float* S1b  = S + OFF_S1;
    float* M2   = S + OFF_M2;
    float* S2b  = S + OFF_S2;
    float* U1A  = S + OFF_U1A;
    float* U1B  = S + OFF_U1B;
    float* U2A  = S + OFF_U2A;
    float* U2B  = S + OFF_U2B;
    float* ep   = S + OFF_EP;

    // 1. embed (merged)
    k_embed<8><<<(B * N1 + B * N2) / 8, 128>>>(h1, h2, W_embed, h1buf[0], h2buf[0]);

    // 2. GAT layers (graph1 + graph2 merged per stage)
    int cur = 0;
    for (int l = 0; l < NL; l++) {
        const float* W  = gW + (size_t)l * D * D;
        const float* Wb = gWb + (size_t)l * D;
        const float* A  = gA + (size_t)l * D * D;
        const float* Gw = gGateW + (size_t)l * 2 * D;
        const float* Gb = gGateb + l;
        int nxt = cur ^ 1;
        k_h_hA<8><<<(B * N1 + B * N2) / 8, 128>>>(h1buf[cur], h2buf[cur], W, Wb, A,
                                                  t1, ta1, t2, ta2);
        k_Egemm<<<288 + 8, 256>>>(ta2, t2, adj2, E2, ta1, t1, adj1, E1);
        k_colstats<<<128 + 16, 512>>>(E2, M2, S2b, E1, M1, S1b);
        k_hp_gate<<<256 + 32, 128>>>(h2buf[cur], t2, E2, M2, S2b,
                                     h1buf[cur], t1, E1, M1, S1b,
                                     Gw, Gb, h2buf[nxt], h1buf[nxt]);
        cur = nxt;
    }
    const float* h1e = h1buf[cur];
    const float* h2e = h2buf[cur];

    // 3. factored MLP first layer (merged)
    k_precU<<<7 * ((B * N1 + B * N2) / TMU), 128>>>(h1e, h2e, WA1, bA1, WB1, bB1,
                                                    U1A, U1B, U2A, U2B);

    // 4. intercept (initializes out), sparse energies (dm inline), reduce
    k_intercept<<<B, 128>>>(h1e, valid, Wi1, bi1, Wi2, bi2, out);
    k_energy<<<B * NT * N1, 128>>>(U1A, U1B, U2A, U2B, WA2, bA2, WB2, bB2,
                                   Cc, A_int, dmv, ep);
    k_reduce<<<1, 64>>>(ep, out);
}